// round 7
// baseline (speedup 1.0000x reference)
#include <cuda_runtime.h>
#include <cstdint>

#define T_STEPS 1024
#define BATCH   1024
#define INDIM   128
#define HID     16
#define NROWS   (T_STEPS * BATCH)

#define NBLOCKS     128
#define TPB         512
#define GEMM_TPB    256                  // warps 8..15
#define PASS_T      16                   // timesteps produced per pass
#define NPASS       (T_STEPS / PASS_T)   // 64
#define ROWS_PASS   (PASS_T * BATCH)     // 16384
#define WARPS_GEMM  (NBLOCKS * GEMM_TPB / 32)  // 1024 producer warps

// Scratch: per-(t,b) input projections, 4 gates x 16 hidden = 64 floats/row.
// Layout: g_proj[row*64 + gate*16 + n], row = t*BATCH + b. One pad timestep.
__device__ float g_proj[(size_t)(NROWS + BATCH) * 64];
// Per-pass completion counters (reset by cudaMemsetAsync each launch).
__device__ int g_cnt[NPASS];

// ---------------- packed f32x2 helpers (sm_103a FFMA2 path) ----------------
__device__ __forceinline__ unsigned long long pack2(float x, float y) {
    unsigned long long r;
    asm("mov.b64 %0, {%1, %2};" : "=l"(r) : "f"(x), "f"(y));
    return r;
}
__device__ __forceinline__ unsigned long long ffma2(unsigned long long a,
                                                    unsigned long long b,
                                                    unsigned long long c) {
    unsigned long long d;
    asm("fma.rn.f32x2 %0, %1, %2, %3;" : "=l"(d) : "l"(a), "l"(b), "l"(c));
    return d;
}
__device__ __forceinline__ float2 unpack2(unsigned long long v) {
    float2 f;
    asm("mov.b64 {%0, %1}, %2;" : "=f"(f.x), "=f"(f.y) : "l"(v));
    return f;
}
__device__ __forceinline__ int ld_acq(const int* p) {
    int v;
    asm volatile("ld.acquire.gpu.global.b32 %0, [%1];" : "=r"(v) : "l"(p) : "memory");
    return v;
}

// ---------------- fast activations ----------------
__device__ __forceinline__ float fsigmoid(float x) {
    return __fdividef(1.f, 1.f + __expf(-x));
}
__device__ __forceinline__ float ftanh(float x) {
    float e = __expf(-2.f * x);
    return __fdividef(1.f - e, 1.f + e);
}

// ======================= fused producer/consumer kernel =====================
__global__ void __launch_bounds__(TPB, 1) fused(
    const float* __restrict__ x,
    const float* __restrict__ Wf, const float* __restrict__ bf,
    const float* __restrict__ thf,
    const float* __restrict__ Wi, const float* __restrict__ bi,
    const float* __restrict__ thi,
    const float* __restrict__ Wg, const float* __restrict__ bg,
    const float* __restrict__ thg,
    const float* __restrict__ Wo, const float* __restrict__ bo,
    const float* __restrict__ tho,
    float* __restrict__ out)
{
    // Shared: input-projection weights, [k][n-pair] as f32x2, n = gate*16+j.
    __shared__ unsigned long long Wsh[128][32];
    __shared__ float bsh[64];

    int tid = threadIdx.x;
    {
        const float* Ws[4] = {Wf, Wi, Wg, Wo};
        float* Wflat = (float*)Wsh;  // Wflat[k*64 + n]
        for (int idx = tid; idx < 64 * 128; idx += TPB) {
            int n = idx >> 7;
            int k = idx & 127;
            Wflat[k * 64 + n] = Ws[n >> 4][(n & 15) * 144 + k];
        }
        if (tid < 64) {
            const float* bp = (tid < 16) ? bf : (tid < 32) ? bi : (tid < 48) ? bg : bo;
            bsh[tid] = bp[tid & 15];
        }
    }
    __syncthreads();

    int wid = tid >> 5;

    if (wid >= 8) {
        // =================== producer: input projection GEMM ===============
        // 2 threads per row; thread computes 32 of the 64 outputs.
        int g = tid - GEMM_TPB;                       // 0..255
        int half = g & 1;                             // output half
        int pairidx = blockIdx.x * (GEMM_TPB / 2) + (g >> 1);
        int lane = tid & 31;

        for (int p = 0; p < NPASS; p++) {
            size_t row = (size_t)p * ROWS_PASS + pairidx;
            const float4* xr = (const float4*)(x + row * (size_t)INDIM);

            unsigned long long acc[16];
#pragma unroll
            for (int q = 0; q < 16; q++) acc[q] = 0ull;

#pragma unroll 2
            for (int kq = 0; kq < 32; kq++) {
                float4 xv = xr[kq];
#pragma unroll
                for (int kk = 0; kk < 4; kk++) {
                    float xs = (kk == 0) ? xv.x : (kk == 1) ? xv.y
                             : (kk == 2) ? xv.z : xv.w;
                    unsigned long long xx = pack2(xs, xs);
                    const ulonglong2* wrow =
                        (const ulonglong2*)&Wsh[kq * 4 + kk][half * 16];
#pragma unroll
                    for (int q = 0; q < 8; q++) {
                        ulonglong2 w = wrow[q];
                        acc[2 * q]     = ffma2(xx, w.x, acc[2 * q]);
                        acc[2 * q + 1] = ffma2(xx, w.y, acc[2 * q + 1]);
                    }
                }
            }

            float* op = g_proj + row * 64 + half * 32;
#pragma unroll
            for (int q = 0; q < 8; q++) {
                float2 a  = unpack2(acc[2 * q]);
                float2 b2 = unpack2(acc[2 * q + 1]);
                float4 o4;
                o4.x = a.x  + bsh[half * 32 + 4 * q + 0];
                o4.y = a.y  + bsh[half * 32 + 4 * q + 1];
                o4.z = b2.x + bsh[half * 32 + 4 * q + 2];
                o4.w = b2.y + bsh[half * 32 + 4 * q + 3];
                ((float4*)op)[q] = o4;
            }

            // Release this pass: canonical fence-all-lanes + one atomic.
            __threadfence();
            __syncwarp();
            if (lane == 0) atomicAdd(&g_cnt[p], 1);
        }
        return;
    }

    // ====================== consumer: the recurrence =======================
    // One warp per batch element. lane l: j = l&15, half = l>>4.
    // half0 owns gates (f,i); half1 owns gates (g,o).
    int b = blockIdx.x * 8 + wid;
    int l = tid & 31;
    int j = l & 15;
    int half = l >> 4;
    int seg = l & 16;
    const unsigned FULL = 0xffffffffu;

    const float* WA = half ? Wg : Wf;
    const float* WB = half ? Wo : Wi;
    float tA = (half ? thg : thf)[j];
    float tB = (half ? tho : thi)[j];

    float wrA[16], wrB[16];
#pragma unroll
    for (int k = 0; k < 16; k++) {
        wrA[k] = WA[j * 144 + 128 + k];
        wrB[k] = WB[j * 144 + 128 + k];
    }

    float h = 0.f, c = 0.f;

    const float* pp = g_proj + (size_t)b * 64 + half * 32 + j;

    // Wait for pass 0, then load step-0 projections.
    {
        const int* a = &g_cnt[0];
        while (ld_acq(a) < WARPS_GEMM) __nanosleep(64);
    }
    float pA = pp[0], pB = pp[16];

    for (int t = 0; t < T_STEPS; t++) {
        const float* pn = pp + BATCH * 64;
        bool bnd = ((t + 1) & (PASS_T - 1)) == 0;
        float nA = 0.f, nB = 0.f;
        if (!bnd) { nA = pn[0]; nB = pn[16]; }   // prefetch (same pass, ready)

        // Recurrent matvec, tree-reduced (4 partials -> short chain).
        float s0A = 0.f, s1A = 0.f, s2A = 0.f, s3A = 0.f;
        float s0B = 0.f, s1B = 0.f, s2B = 0.f, s3B = 0.f;
#pragma unroll
        for (int k = 0; k < 16; k += 4) {
            float h0 = __shfl_sync(FULL, h, seg + k + 0);
            float h1 = __shfl_sync(FULL, h, seg + k + 1);
            float h2 = __shfl_sync(FULL, h, seg + k + 2);
            float h3 = __shfl_sync(FULL, h, seg + k + 3);
            s0A = fmaf(h0, wrA[k + 0], s0A);
            s1A = fmaf(h1, wrA[k + 1], s1A);
            s2A = fmaf(h2, wrA[k + 2], s2A);
            s3A = fmaf(h3, wrA[k + 3], s3A);
            s0B = fmaf(h0, wrB[k + 0], s0B);
            s1B = fmaf(h1, wrB[k + 1], s1B);
            s2B = fmaf(h2, wrB[k + 2], s2B);
            s3B = fmaf(h3, wrB[k + 3], s3B);
        }
        float aA = pA + ((s0A + s1A) + (s2A + s3A));
        float aB = pB + ((s0B + s1B) + (s2B + s3B));

        // qgate: sin then inclusive prefix-sum over the 16-lane segment.
        float sA = __sinf(aA + tA), sB = __sinf(aB + tB);
        float cA = sA, cB = sB;
#pragma unroll
        for (int off = 1; off < 16; off <<= 1) {
            float uA = __shfl_up_sync(FULL, cA, off, 16);
            float uB = __shfl_up_sync(FULL, cB, off, 16);
            if (j >= off) { cA += uA; cB += uB; }
        }
        float ttA = __shfl_sync(FULL, cA, seg + 15);
        float ttB = __shfl_sync(FULL, cB, seg + 15);
        float qA = (j == 0) ? (sA + ttA) : cA;
        float qB = (j == 0) ? (sB + ttB) : cB;

        // half0: sigmoid(qA)=f ; half1: tanh(qA)=g. qB: sigmoid (i or o).
        float eA = __expf(half ? (-2.f * qA) : (-qA));
        float vA = __fdividef(half ? (1.f - eA) : 1.f, 1.f + eA);
        float vB = fsigmoid(qB);

        float oA = __shfl_xor_sync(FULL, vA, 16);
        float oB = __shfl_xor_sync(FULL, vB, 16);
        float f_ = half ? oA : vA;
        float i_ = half ? oB : vB;
        float g_ = half ? vA : oA;
        float o_ = half ? vB : oB;

        c = f_ * c + i_ * g_;
        h = o_ * ftanh(c);

        if (half == 0)
            out[((size_t)t << 14) + (b << 4) + j] = h;

        // Pass boundary: wait for the next pass, then load its first step.
        if (bnd && t != T_STEPS - 1) {
            const int* a = &g_cnt[(t + 1) >> 4];
            while (ld_acq(a) < WARPS_GEMM) __nanosleep(64);
            nA = pn[0]; nB = pn[16];
        }
        pA = nA; pB = nB;
        pp = pn;
    }

    if (half == 0) {
        size_t base = (size_t)T_STEPS * BATCH * HID;
        out[base + (b << 4) + j] = h;
        out[base + BATCH * HID + (b << 4) + j] = c;
    }
}

// ---------------- launch ----------------
extern "C" void kernel_launch(void* const* d_in, const int* in_sizes, int n_in,
                              void* d_out, int out_size) {
    const float* x   = (const float*)d_in[0];
    const float* Wf  = (const float*)d_in[1];
    const float* bf  = (const float*)d_in[2];
    const float* thf = (const float*)d_in[3];
    const float* Wi  = (const float*)d_in[4];
    const float* bi  = (const float*)d_in[5];
    const float* thi = (const float*)d_in[6];
    const float* Wg  = (const float*)d_in[7];
    const float* bg  = (const float*)d_in[8];
    const float* thg = (const float*)d_in[9];
    const float* Wo  = (const float*)d_in[10];
    const float* bo  = (const float*)d_in[11];
    const float* tho = (const float*)d_in[12];
    float* out = (float*)d_out;

    // Reset pass counters (graph-capturable async memset; no allocation).
    void* cnt_addr = nullptr;
    cudaGetSymbolAddress(&cnt_addr, g_cnt);
    cudaMemsetAsync(cnt_addr, 0, sizeof(int) * NPASS);

    fused<<<NBLOCKS, TPB>>>(x, Wf, bf, thf, Wi, bi, thi,
                            Wg, bg, thg, Wo, bo, tho, out);
}

// round 9
// speedup vs baseline: 1.2185x; 1.2185x over previous
#include <cuda_runtime.h>
#include <cuda_bf16.h>
#include <cstdint>

#define T_STEPS 1024
#define BATCH   1024
#define INDIM   128
#define HID     16
#define NROWS   (T_STEPS * BATCH)
#define STRIDE  (BATCH * 64)          // floats per timestep in g_proj

// Scratch: per-(t,b) input projections, 4 gates x 16 hidden = 64 floats/row.
// Layout: g_proj[row*64 + gate*16 + n], row = t*BATCH + b.
// Padded by 4 timesteps for the depth-4 prefetch in the recurrence.
__device__ float g_proj[(size_t)(NROWS + 4 * BATCH) * 64];

// =================== Kernel 1: mma.sync split-bf16 GEMM ====================
// C[row][n] = bias[n] + sum_{k<128} x[row][k] * W[n][k],  n = gate*16+j.
// Split x = xh+xl, W = wh+wl (bf16 hi + bf16 residual); fp32 accumulation:
//   C = xh*wh + xh*wl + xl*wh   (residual term xl*wl ~ 2^-18, dropped)
// mma.sync.m16n8k16.row.col.f32.bf16.bf16.f32 standard fragment layouts:
//   A (16x16 row-major):  g=lane>>2, t=lane&3
//     a0={A[g][2t],A[g][2t+1]}  a1=rows+8  a2=cols+8  a3=rows+8,cols+8
//   B (16x8, B[k][n]=W[n][k]): b0={B[2t][g],B[2t+1][g]}  b1=k+8
//   C (16x8 f32): c0=C[g][2t] c1=C[g][2t+1] c2,c3=rows+8
// Fragments are PRE-PACKED into smem in per-lane order so the mainloop does
// one LDS.128 per A-frag and one LDS.64 per B-frag.
//
// CTA = 128 threads (4 warps). Warp tile: M=32 (2 m-tiles), N=64, K=128.
// CTA tile: M=128.  Grid = 8192.
#define SM_BIAS 0
#define SM_BF   256                       // B frags: 2 splits*8nt*8s*32ln*8B = 32KB
#define SM_AF   (256 + 32768)             // A frags: 4 warps * 16KB
#define SM_TOT  (SM_AF + 4 * 16384)       // 98560 B

__device__ __forceinline__ uint32_t pack_bf2(__nv_bfloat16 lo, __nv_bfloat16 hi) {
    return ((uint32_t)__bfloat16_as_ushort(hi) << 16) | __bfloat16_as_ushort(lo);
}

__global__ void __launch_bounds__(128) proj_mma(
    const float* __restrict__ x,
    const float* __restrict__ Wf, const float* __restrict__ bf_,
    const float* __restrict__ Wi, const float* __restrict__ bi_,
    const float* __restrict__ Wg, const float* __restrict__ bg_,
    const float* __restrict__ Wo, const float* __restrict__ bo_)
{
    extern __shared__ char smem[];
    int tid = threadIdx.x, warp = tid >> 5, lane = tid & 31;

    // ---- bias -> smem ----
    if (tid < 64) {
        const float* bp = (tid < 16) ? bf_ : (tid < 32) ? bi_
                        : (tid < 48) ? bg_ : bo_;
        ((float*)(smem + SM_BIAS))[tid] = bp[tid & 15];
    }

    // ---- B fragments (weights), written once, flat word w = tid + 128*i ----
    // word index = ((split*64 + nt*8 + s)*32 + ln)*2 + reg
    {
        const float* Wp[4] = {Wf, Wi, Wg, Wo};
        for (int i = 0; i < 64; i++) {
            int w = tid + 128 * i;
            int split = w >> 12;
            int nt = (w >> 9) & 7, s = (w >> 6) & 7;
            int ln = (w >> 1) & 31, reg = w & 1;
            int n = nt * 8 + (ln >> 2);
            int k0 = s * 16 + (ln & 3) * 2 + reg * 8;
            const float* wr = Wp[n >> 4] + (n & 15) * 144 + k0;
            float v0 = wr[0], v1 = wr[1];
            __nv_bfloat16 h0 = __float2bfloat16_rn(v0);
            __nv_bfloat16 h1 = __float2bfloat16_rn(v1);
            uint32_t outw;
            if (split == 0) {
                outw = pack_bf2(h0, h1);
            } else {
                __nv_bfloat16 l0 = __float2bfloat16_rn(v0 - __bfloat162float(h0));
                __nv_bfloat16 l1 = __float2bfloat16_rn(v1 - __bfloat162float(h1));
                outw = pack_bf2(l0, l1);
            }
            *(uint32_t*)(smem + SM_BF + w * 4) = outw;
        }
    }

    // ---- A fragments: convert this warp's 32 rows, write in frag order ----
    // Store slot is bank-swizzled with s (slot = lane' ^ (s&7)); the reader
    // applies the same XOR, so it's a transparent permutation.
    size_t rowbase = (size_t)blockIdx.x * 128 + warp * 32;
    {
        uint32_t abase = SM_AF + warp * 16384;
        for (int i = 0; i < 32; i++) {
            int rr = i & 15, mt = i >> 4;
            float4 v = ((const float4*)x)[(rowbase + i) * 32 + lane];
#pragma unroll
            for (int pi = 0; pi < 2; pi++) {
                float e0 = pi ? v.z : v.x;
                float e1 = pi ? v.w : v.y;
                int k0 = 4 * lane + 2 * pi;
                int s = k0 >> 4, ko = k0 & 15;
                int t = (ko >> 1) & 3, hi4 = ko >> 3;
                int reg = (rr >> 3) + 2 * hi4;
                int slot = ((rr & 7) * 4 + t) ^ (s & 7);
                __nv_bfloat16 h0 = __float2bfloat16_rn(e0);
                __nv_bfloat16 h1 = __float2bfloat16_rn(e1);
                __nv_bfloat16 l0 = __float2bfloat16_rn(e0 - __bfloat162float(h0));
                __nv_bfloat16 l1 = __float2bfloat16_rn(e1 - __bfloat162float(h1));
                *(uint32_t*)(smem + abase +
                    ((((0 * 16 + mt * 8 + s) * 32) + slot) << 4) + reg * 4)
                    = pack_bf2(h0, h1);
                *(uint32_t*)(smem + abase +
                    ((((1 * 16 + mt * 8 + s) * 32) + slot) << 4) + reg * 4)
                    = pack_bf2(l0, l1);
            }
        }
    }
    __syncthreads();

    // ---- mainloop: 3 combos x 8 k-steps x (2 m-tiles x 8 n-tiles) mma ----
    float acc[2][8][4];
#pragma unroll
    for (int mt = 0; mt < 2; mt++)
#pragma unroll
        for (int nt = 0; nt < 8; nt++)
#pragma unroll
            for (int r = 0; r < 4; r++) acc[mt][nt][r] = 0.f;

#pragma unroll 1
    for (int cmb = 0; cmb < 3; cmb++) {
        int asplit = (cmb == 2) ? 1 : 0;
        int bsplit = (cmb == 1) ? 1 : 0;
#pragma unroll 1
        for (int s = 0; s < 8; s++) {
            uint4 af[2];
#pragma unroll
            for (int mt = 0; mt < 2; mt++)
                af[mt] = *(const uint4*)(smem + SM_AF + warp * 16384 +
                    ((((asplit * 16 + mt * 8 + s) * 32) + (lane ^ (s & 7))) << 4));
#pragma unroll
            for (int nt = 0; nt < 8; nt++) {
                uint2 bfrag = *(const uint2*)(smem + SM_BF +
                    ((((bsplit * 64 + nt * 8 + s) * 32) + lane) << 3));
#pragma unroll
                for (int mt = 0; mt < 2; mt++) {
                    asm volatile(
                        "mma.sync.aligned.m16n8k16.row.col.f32.bf16.bf16.f32 "
                        "{%0,%1,%2,%3}, {%4,%5,%6,%7}, {%8,%9}, {%0,%1,%2,%3};"
                        : "+f"(acc[mt][nt][0]), "+f"(acc[mt][nt][1]),
                          "+f"(acc[mt][nt][2]), "+f"(acc[mt][nt][3])
                        : "r"(af[mt].x), "r"(af[mt].y),
                          "r"(af[mt].z), "r"(af[mt].w),
                          "r"(bfrag.x), "r"(bfrag.y));
                }
            }
        }
    }

    // ---- epilogue: + bias, store f32 pairs ----
    int g = lane >> 2, t = lane & 3;
#pragma unroll
    for (int mt = 0; mt < 2; mt++) {
#pragma unroll
        for (int nt = 0; nt < 8; nt++) {
            int col = nt * 8 + t * 2;
            float2 bb = *(const float2*)(smem + SM_BIAS + col * 4);
            size_t r0 = rowbase + mt * 16 + g;
            float2 o0, o1;
            o0.x = acc[mt][nt][0] + bb.x;
            o0.y = acc[mt][nt][1] + bb.y;
            o1.x = acc[mt][nt][2] + bb.x;
            o1.y = acc[mt][nt][3] + bb.y;
            *(float2*)(g_proj + r0 * 64 + col) = o0;
            *(float2*)(g_proj + (r0 + 8) * 64 + col) = o1;
        }
    }
}

// ---------------- fast activations ----------------
__device__ __forceinline__ float fsigmoid(float x) {
    return __fdividef(1.f, 1.f + __expf(-x));
}
__device__ __forceinline__ float ftanh(float x) {
    float e = __expf(-2.f * x);
    return __fdividef(1.f - e, 1.f + e);
}

// ==================== Kernel 2: recurrence, depth-4 prefetch ===============
// One warp per batch element; lane l: j=l&15 hidden unit, half=l>>4.
// half0 owns gates (f,i); half1 owns (g,o); exchange via shfl_xor(16).
__global__ void __launch_bounds__(128) recur(
    const float* __restrict__ Wf, const float* __restrict__ Wi,
    const float* __restrict__ Wg, const float* __restrict__ Wo,
    const float* __restrict__ thf, const float* __restrict__ thi,
    const float* __restrict__ thg, const float* __restrict__ tho,
    float* __restrict__ out)
{
    int wid = threadIdx.x >> 5;
    int b = blockIdx.x * 4 + wid;
    int l = threadIdx.x & 31;
    int j = l & 15;
    int half = l >> 4;
    int seg = l & 16;
    const unsigned FULL = 0xffffffffu;

    const float* WA = half ? Wg : Wf;
    const float* WB = half ? Wo : Wi;
    float tA = (half ? thg : thf)[j];
    float tB = (half ? tho : thi)[j];

    float wrA[16], wrB[16];
#pragma unroll
    for (int k = 0; k < 16; k++) {
        wrA[k] = WA[j * 144 + 128 + k];
        wrB[k] = WB[j * 144 + 128 + k];
    }

    float h = 0.f, c = 0.f;
    const float* pp = g_proj + (size_t)b * 64 + half * 32 + j;

    // Preload group 0 (steps 0..3)
    float curA[4], curB[4];
#pragma unroll
    for (int u = 0; u < 4; u++) {
        curA[u] = pp[(size_t)u * STRIDE];
        curB[u] = pp[(size_t)u * STRIDE + 16];
    }

    for (int g = 0; g < T_STEPS / 4; g++) {
        // Prefetch next group (rows exist thanks to the 4-step pad)
        float nA[4], nB[4];
#pragma unroll
        for (int u = 0; u < 4; u++) {
            nA[u] = pp[(size_t)(4 + u) * STRIDE];
            nB[u] = pp[(size_t)(4 + u) * STRIDE + 16];
        }

#pragma unroll
        for (int u = 0; u < 4; u++) {
            int t = g * 4 + u;

            // Recurrent matvec, tree-reduced
            float s0A = 0.f, s1A = 0.f, s2A = 0.f, s3A = 0.f;
            float s0B = 0.f, s1B = 0.f, s2B = 0.f, s3B = 0.f;
#pragma unroll
            for (int k = 0; k < 16; k += 4) {
                float h0 = __shfl_sync(FULL, h, seg + k + 0);
                float h1 = __shfl_sync(FULL, h, seg + k + 1);
                float h2 = __shfl_sync(FULL, h, seg + k + 2);
                float h3 = __shfl_sync(FULL, h, seg + k + 3);
                s0A = fmaf(h0, wrA[k + 0], s0A);
                s1A = fmaf(h1, wrA[k + 1], s1A);
                s2A = fmaf(h2, wrA[k + 2], s2A);
                s3A = fmaf(h3, wrA[k + 3], s3A);
                s0B = fmaf(h0, wrB[k + 0], s0B);
                s1B = fmaf(h1, wrB[k + 1], s1B);
                s2B = fmaf(h2, wrB[k + 2], s2B);
                s3B = fmaf(h3, wrB[k + 3], s3B);
            }
            float aA = curA[u] + ((s0A + s1A) + (s2A + s3A));
            float aB = curB[u] + ((s0B + s1B) + (s2B + s3B));

            // qgate: sin + 16-lane inclusive scan
            float sA = __sinf(aA + tA), sB = __sinf(aB + tB);
            float cA = sA, cB = sB;
#pragma unroll
            for (int off = 1; off < 16; off <<= 1) {
                float uA = __shfl_up_sync(FULL, cA, off, 16);
                float uB = __shfl_up_sync(FULL, cB, off, 16);
                if (j >= off) { cA += uA; cB += uB; }
            }
            float ttA = __shfl_sync(FULL, cA, seg + 15);
            float ttB = __shfl_sync(FULL, cB, seg + 15);
            float qA = (j == 0) ? (sA + ttA) : cA;
            float qB = (j == 0) ? (sB + ttB) : cB;

            // half0: sigmoid(qA)=f ; half1: tanh(qA)=g ; qB sigmoid (i or o)
            float eA = __expf(half ? (-2.f * qA) : (-qA));
            float vA = __fdividef(half ? (1.f - eA) : 1.f, 1.f + eA);
            float vB = fsigmoid(qB);

            float oA = __shfl_xor_sync(FULL, vA, 16);
            float oB = __shfl_xor_sync(FULL, vB, 16);
            float f_ = half ? oA : vA;
            float i_ = half ? oB : vB;
            float g_ = half ? vA : oA;
            float o_ = half ? vB : oB;

            c = f_ * c + i_ * g_;
            h = o_ * ftanh(c);

            if (half == 0)
                out[((size_t)t << 14) + (b << 4) + j] = h;
        }

#pragma unroll
        for (int u = 0; u < 4; u++) { curA[u] = nA[u]; curB[u] = nB[u]; }
        pp += (size_t)4 * STRIDE;
    }

    if (half == 0) {
        size_t base = (size_t)T_STEPS * BATCH * HID;
        out[base + (b << 4) + j] = h;
        out[base + BATCH * HID + (b << 4) + j] = c;
    }
}

// ---------------- launch ----------------
extern "C" void kernel_launch(void* const* d_in, const int* in_sizes, int n_in,
                              void* d_out, int out_size) {
    const float* x   = (const float*)d_in[0];
    const float* Wf  = (const float*)d_in[1];
    const float* bf_ = (const float*)d_in[2];
    const float* thf = (const float*)d_in[3];
    const float* Wi  = (const float*)d_in[4];
    const float* bi_ = (const float*)d_in[5];
    const float* thi = (const float*)d_in[6];
    const float* Wg  = (const float*)d_in[7];
    const float* bg_ = (const float*)d_in[8];
    const float* thg = (const float*)d_in[9];
    const float* Wo  = (const float*)d_in[10];
    const float* bo_ = (const float*)d_in[11];
    const float* tho = (const float*)d_in[12];
    float* out = (float*)d_out;

    cudaFuncSetAttribute(proj_mma,
                         cudaFuncAttributeMaxDynamicSharedMemorySize, SM_TOT);

    proj_mma<<<NROWS / 128, 128, SM_TOT>>>(x, Wf, bf_, Wi, bi_,
                                           Wg, bg_, Wo, bo_);
    recur<<<BATCH / 4, 128>>>(Wf, Wi, Wg, Wo, thf, thi, thg, tho, out);
}

// round 10
// speedup vs baseline: 1.5600x; 1.2803x over previous
#include <cuda_runtime.h>
#include <cuda_bf16.h>
#include <cstdint>

#define T_STEPS 1024
#define BATCH   1024
#define INDIM   128
#define HID     16
#define NROWS   (T_STEPS * BATCH)
#define STRIDE  (BATCH * 64)          // floats per timestep in g_proj

// Scratch: per-(t,b) input projections, 4 gates x 16 hidden = 64 floats/row.
// Layout: g_proj[row*64 + gate*16 + n], row = t*BATCH + b.
// Padded by 4 timesteps for the depth-4 prefetch in the recurrence.
__device__ float g_proj[(size_t)(NROWS + 4 * BATCH) * 64];
// Pre-packed B (weight) mma fragments: 2 splits x 8 nt x 8 s x 32 lanes x 2 regs.
__device__ uint32_t g_bfrag[8192];

__device__ __forceinline__ uint32_t pack_bf2(__nv_bfloat16 lo, __nv_bfloat16 hi) {
    return ((uint32_t)__bfloat16_as_ushort(hi) << 16) | __bfloat16_as_ushort(lo);
}

// =============== Kernel 0: one-shot W -> B-fragment conversion =============
// word index w = ((split*64 + nt*8 + s)*32 + ln)*2 + reg
// B fragment (m16n8k16.row.col): b0={B[2t][g],B[2t+1][g]}, b1 = k+8; g=ln>>2,
// t=ln&3, B[k][n] = W[n][k].
__global__ void __launch_bounds__(128) prep_bfrag(
    const float* __restrict__ Wf, const float* __restrict__ Wi,
    const float* __restrict__ Wg, const float* __restrict__ Wo)
{
    int w = blockIdx.x * 128 + threadIdx.x;
    int split = w >> 12;
    int nt = (w >> 9) & 7, s = (w >> 6) & 7;
    int ln = (w >> 1) & 31, reg = w & 1;
    int n = nt * 8 + (ln >> 2);
    int k0 = s * 16 + (ln & 3) * 2 + reg * 8;
    const float* wr = ((n < 16) ? Wf : (n < 32) ? Wi : (n < 48) ? Wg : Wo)
                      + (n & 15) * 144 + k0;
    float v0 = wr[0], v1 = wr[1];
    __nv_bfloat16 h0 = __float2bfloat16_rn(v0);
    __nv_bfloat16 h1 = __float2bfloat16_rn(v1);
    uint32_t outw;
    if (split == 0) {
        outw = pack_bf2(h0, h1);
    } else {
        __nv_bfloat16 l0 = __float2bfloat16_rn(v0 - __bfloat162float(h0));
        __nv_bfloat16 l1 = __float2bfloat16_rn(v1 - __bfloat162float(h1));
        outw = pack_bf2(l0, l1);
    }
    g_bfrag[w] = outw;
}

// =================== Kernel 1: mma.sync split-bf16 GEMM ====================
// C[row][n] = bias[n] + sum_{k<128} x[row][k]*W[n][k].  Split x=xh+xl, W=wh+wl;
// C = xh*wh + xh*wl + xl*wh (fp32 accum; dropped xl*wl ~ 2^-18).
// CTA = 128 threads (4 warps). Warp tile M=32 (2 m-tiles) x N=64 x K=128.
#define SM_BIAS 0
#define SM_BF   256                       // B frags copied from g_bfrag (32KB)
#define SM_AF   (256 + 32768)             // A frags: 4 warps * 16KB
#define SM_TOT  (SM_AF + 4 * 16384)       // 98560 B

__global__ void __launch_bounds__(128) proj_mma(
    const float* __restrict__ x,
    const float* __restrict__ bf_, const float* __restrict__ bi_,
    const float* __restrict__ bg_, const float* __restrict__ bo_)
{
    extern __shared__ char smem[];
    int tid = threadIdx.x, warp = tid >> 5, lane = tid & 31;

    // ---- bias -> smem ----
    if (tid < 64) {
        const float* bp = (tid < 16) ? bf_ : (tid < 32) ? bi_
                        : (tid < 48) ? bg_ : bo_;
        ((float*)(smem + SM_BIAS))[tid] = bp[tid & 15];
    }

    // ---- B fragments: coalesced copy from g_bfrag (L2-resident 32KB) ----
#pragma unroll
    for (int i = 0; i < 16; i++)
        ((uint4*)(smem + SM_BF))[tid + 128 * i] =
            ((const uint4*)g_bfrag)[tid + 128 * i];

    // ---- A fragments: convert this warp's 32 rows, write in frag order ----
    // slot is bank-swizzled with s (slot = lane' ^ (s&7)); reader applies the
    // same XOR -> transparent permutation.
    size_t rowbase = (size_t)blockIdx.x * 128 + warp * 32;
    {
        uint32_t abase = SM_AF + warp * 16384;
        for (int i = 0; i < 32; i++) {
            int rr = i & 15, mt = i >> 4;
            float4 v = ((const float4*)x)[(rowbase + i) * 32 + lane];
#pragma unroll
            for (int pi = 0; pi < 2; pi++) {
                float e0 = pi ? v.z : v.x;
                float e1 = pi ? v.w : v.y;
                int k0 = 4 * lane + 2 * pi;
                int s = k0 >> 4, ko = k0 & 15;
                int t = (ko >> 1) & 3, hi4 = ko >> 3;
                int reg = (rr >> 3) + 2 * hi4;
                int slot = ((rr & 7) * 4 + t) ^ (s & 7);
                __nv_bfloat16 h0 = __float2bfloat16_rn(e0);
                __nv_bfloat16 h1 = __float2bfloat16_rn(e1);
                __nv_bfloat16 l0 = __float2bfloat16_rn(e0 - __bfloat162float(h0));
                __nv_bfloat16 l1 = __float2bfloat16_rn(e1 - __bfloat162float(h1));
                *(uint32_t*)(smem + abase +
                    ((((0 * 16 + mt * 8 + s) * 32) + slot) << 4) + reg * 4)
                    = pack_bf2(h0, h1);
                *(uint32_t*)(smem + abase +
                    ((((1 * 16 + mt * 8 + s) * 32) + slot) << 4) + reg * 4)
                    = pack_bf2(l0, l1);
            }
        }
    }
    __syncthreads();

    // ---- mainloop: 3 combos x 8 k-steps x (2 m-tiles x 8 n-tiles) mma ----
    float acc[2][8][4];
#pragma unroll
    for (int mt = 0; mt < 2; mt++)
#pragma unroll
        for (int nt = 0; nt < 8; nt++)
#pragma unroll
            for (int r = 0; r < 4; r++) acc[mt][nt][r] = 0.f;

#pragma unroll 1
    for (int cmb = 0; cmb < 3; cmb++) {
        int asplit = (cmb == 2) ? 1 : 0;
        int bsplit = (cmb == 1) ? 1 : 0;
#pragma unroll 1
        for (int s = 0; s < 8; s++) {
            uint4 af[2];
#pragma unroll
            for (int mt = 0; mt < 2; mt++)
                af[mt] = *(const uint4*)(smem + SM_AF + warp * 16384 +
                    ((((asplit * 16 + mt * 8 + s) * 32) + (lane ^ (s & 7))) << 4));
#pragma unroll
            for (int nt = 0; nt < 8; nt++) {
                uint2 bfrag = *(const uint2*)(smem + SM_BF +
                    ((((bsplit * 64 + nt * 8 + s) * 32) + lane) << 3));
#pragma unroll
                for (int mt = 0; mt < 2; mt++) {
                    asm volatile(
                        "mma.sync.aligned.m16n8k16.row.col.f32.bf16.bf16.f32 "
                        "{%0,%1,%2,%3}, {%4,%5,%6,%7}, {%8,%9}, {%0,%1,%2,%3};"
                        : "+f"(acc[mt][nt][0]), "+f"(acc[mt][nt][1]),
                          "+f"(acc[mt][nt][2]), "+f"(acc[mt][nt][3])
                        : "r"(af[mt].x), "r"(af[mt].y),
                          "r"(af[mt].z), "r"(af[mt].w),
                          "r"(bfrag.x), "r"(bfrag.y));
                }
            }
        }
    }

    // ---- epilogue: + bias, store f32 pairs ----
    int g = lane >> 2, t = lane & 3;
#pragma unroll
    for (int mt = 0; mt < 2; mt++) {
#pragma unroll
        for (int nt = 0; nt < 8; nt++) {
            int col = nt * 8 + t * 2;
            float2 bb = *(const float2*)(smem + SM_BIAS + col * 4);
            size_t r0 = rowbase + mt * 16 + g;
            float2 o0, o1;
            o0.x = acc[mt][nt][0] + bb.x;
            o0.y = acc[mt][nt][1] + bb.y;
            o1.x = acc[mt][nt][2] + bb.x;
            o1.y = acc[mt][nt][3] + bb.y;
            *(float2*)(g_proj + r0 * 64 + col) = o0;
            *(float2*)(g_proj + (r0 + 8) * 64 + col) = o1;
        }
    }
}

// ---------------- fast activations ----------------
__device__ __forceinline__ float fsigmoid(float x) {
    return __fdividef(1.f, 1.f + __expf(-x));
}
__device__ __forceinline__ float ftanh(float x) {
    float e = __expf(-2.f * x);
    return __fdividef(1.f - e, 1.f + e);
}
// Predicated store: no BSSY/BSYNC divergence region.
__device__ __forceinline__ void st_pred(float* p, float v, int pred) {
    asm volatile("{\n\t.reg .pred p;\n\tsetp.ne.s32 p, %2, 0;\n\t"
                 "@p st.global.f32 [%0], %1;\n\t}"
                 :: "l"(p), "f"(v), "r"(pred) : "memory");
}

// ==================== Kernel 2: recurrence, depth-4 prefetch ===============
// One warp per batch element; lane l: j=l&15 hidden unit, half=l>>4.
// half0 owns gates (f,i); half1 owns (g,o); exchange via shfl_xor(16).
// All per-step control flow is branchless (selects + predicated stores).
__global__ void __launch_bounds__(128) recur(
    const float* __restrict__ Wf, const float* __restrict__ Wi,
    const float* __restrict__ Wg, const float* __restrict__ Wo,
    const float* __restrict__ thf, const float* __restrict__ thi,
    const float* __restrict__ thg, const float* __restrict__ tho,
    float* __restrict__ out)
{
    int wid = threadIdx.x >> 5;
    int b = blockIdx.x * 4 + wid;
    int l = threadIdx.x & 31;
    int j = l & 15;
    int half = l >> 4;
    int seg = l & 16;
    const unsigned FULL = 0xffffffffu;

    const float* WA = half ? Wg : Wf;
    const float* WB = half ? Wo : Wi;
    float tA = (half ? thg : thf)[j];
    float tB = (half ? tho : thi)[j];

    float wrA[16], wrB[16];
#pragma unroll
    for (int k = 0; k < 16; k++) {
        wrA[k] = WA[j * 144 + 128 + k];
        wrB[k] = WB[j * 144 + 128 + k];
    }

    float h = 0.f, c = 0.f;
    const float* pp = g_proj + (size_t)b * 64 + half * 32 + j;
    float* outp = out + (b << 4) + j;
    int store_h = (half == 0);

    // Preload group 0 (steps 0..3)
    float curA[4], curB[4];
#pragma unroll
    for (int u = 0; u < 4; u++) {
        curA[u] = pp[(size_t)u * STRIDE];
        curB[u] = pp[(size_t)u * STRIDE + 16];
    }

    for (int g = 0; g < T_STEPS / 4; g++) {
        // Prefetch next group (rows exist thanks to the 4-step pad)
        float nA[4], nB[4];
#pragma unroll
        for (int u = 0; u < 4; u++) {
            nA[u] = pp[(size_t)(4 + u) * STRIDE];
            nB[u] = pp[(size_t)(4 + u) * STRIDE + 16];
        }

#pragma unroll
        for (int u = 0; u < 4; u++) {
            // Recurrent matvec, tree-reduced
            float s0A = 0.f, s1A = 0.f, s2A = 0.f, s3A = 0.f;
            float s0B = 0.f, s1B = 0.f, s2B = 0.f, s3B = 0.f;
#pragma unroll
            for (int k = 0; k < 16; k += 4) {
                float h0 = __shfl_sync(FULL, h, seg + k + 0);
                float h1 = __shfl_sync(FULL, h, seg + k + 1);
                float h2 = __shfl_sync(FULL, h, seg + k + 2);
                float h3 = __shfl_sync(FULL, h, seg + k + 3);
                s0A = fmaf(h0, wrA[k + 0], s0A);
                s1A = fmaf(h1, wrA[k + 1], s1A);
                s2A = fmaf(h2, wrA[k + 2], s2A);
                s3A = fmaf(h3, wrA[k + 3], s3A);
                s0B = fmaf(h0, wrB[k + 0], s0B);
                s1B = fmaf(h1, wrB[k + 1], s1B);
                s2B = fmaf(h2, wrB[k + 2], s2B);
                s3B = fmaf(h3, wrB[k + 3], s3B);
            }
            float aA = curA[u] + ((s0A + s1A) + (s2A + s3A));
            float aB = curB[u] + ((s0B + s1B) + (s2B + s3B));

            // qgate: sin + 16-lane inclusive scan (branchless rounds)
            float sA = __sinf(aA + tA), sB = __sinf(aB + tB);
            float cA = sA, cB = sB;
#pragma unroll
            for (int off = 1; off < 16; off <<= 1) {
                float uA = __shfl_up_sync(FULL, cA, off, 16);
                float uB = __shfl_up_sync(FULL, cB, off, 16);
                cA += (j >= off) ? uA : 0.f;
                cB += (j >= off) ? uB : 0.f;
            }
            float ttA = __shfl_sync(FULL, cA, seg + 15);
            float ttB = __shfl_sync(FULL, cB, seg + 15);
            float qA = (j == 0) ? (sA + ttA) : cA;
            float qB = (j == 0) ? (sB + ttB) : cB;

            // half0: sigmoid(qA)=f ; half1: tanh(qA)=g ; qB sigmoid (i or o)
            float eA = __expf(half ? (-2.f * qA) : (-qA));
            float vA = __fdividef(half ? (1.f - eA) : 1.f, 1.f + eA);
            float vB = fsigmoid(qB);

            float oA = __shfl_xor_sync(FULL, vA, 16);
            float oB = __shfl_xor_sync(FULL, vB, 16);
            float f_ = half ? oA : vA;
            float i_ = half ? oB : vB;
            float g_ = half ? vA : oA;
            float o_ = half ? vB : oB;

            c = f_ * c + i_ * g_;
            h = o_ * ftanh(c);

            st_pred(outp, h, store_h);
            outp += BATCH * HID;
        }

#pragma unroll
        for (int u = 0; u < 4; u++) { curA[u] = nA[u]; curB[u] = nB[u]; }
        pp += (size_t)4 * STRIDE;
    }

    size_t base = (size_t)T_STEPS * BATCH * HID;
    st_pred(out + base + (b << 4) + j, h, store_h);
    st_pred(out + base + BATCH * HID + (b << 4) + j, c, store_h);
}

// ---------------- launch ----------------
extern "C" void kernel_launch(void* const* d_in, const int* in_sizes, int n_in,
                              void* d_out, int out_size) {
    const float* x   = (const float*)d_in[0];
    const float* Wf  = (const float*)d_in[1];
    const float* bf_ = (const float*)d_in[2];
    const float* thf = (const float*)d_in[3];
    const float* Wi  = (const float*)d_in[4];
    const float* bi_ = (const float*)d_in[5];
    const float* thi = (const float*)d_in[6];
    const float* Wg  = (const float*)d_in[7];
    const float* bg_ = (const float*)d_in[8];
    const float* thg = (const float*)d_in[9];
    const float* Wo  = (const float*)d_in[10];
    const float* bo_ = (const float*)d_in[11];
    const float* tho = (const float*)d_in[12];
    float* out = (float*)d_out;

    cudaFuncSetAttribute(proj_mma,
                         cudaFuncAttributeMaxDynamicSharedMemorySize, SM_TOT);

    prep_bfrag<<<64, 128>>>(Wf, Wi, Wg, Wo);
    proj_mma<<<NROWS / 128, 128, SM_TOT>>>(x, bf_, bi_, bg_, bo_);
    recur<<<BATCH / 4, 128>>>(Wf, Wi, Wg, Wo, thf, thi, thg, tho, out);
}

// round 12
// speedup vs baseline: 2.1464x; 1.3759x over previous
#include <cuda_runtime.h>
#include <cuda_bf16.h>
#include <cstdint>

#define T_STEPS 1024
#define BATCH   1024
#define INDIM   128
#define HID     16
#define NROWS   (T_STEPS * BATCH)
#define STRIDE  (BATCH * 64)          // floats per timestep in g_proj

// Scratch: per-(t,b) input projections, 4 gates x 16 hidden = 64 floats/row.
// Layout: g_proj[row*64 + gate*16 + n], row = t*BATCH + b.
// Padded by 4 timesteps for the depth-4 prefetch in the recurrence.
__device__ float g_proj[(size_t)(NROWS + 4 * BATCH) * 64];
// Pre-packed B (weight) mma fragments: 2 splits x 8 nt x 8 s x 32 lanes x 2 regs.
__device__ uint32_t g_bfrag[8192];

__device__ __forceinline__ uint32_t pack_bf2(__nv_bfloat16 lo, __nv_bfloat16 hi) {
    return ((uint32_t)__bfloat16_as_ushort(hi) << 16) | __bfloat16_as_ushort(lo);
}
// packed = { lo16 = bf16(losrc), hi16 = bf16(hisrc) }
__device__ __forceinline__ uint32_t cvt_pair(float hisrc, float losrc) {
    uint32_t r;
    asm("cvt.rn.bf16x2.f32 %0, %1, %2;" : "=r"(r) : "f"(hisrc), "f"(losrc));
    return r;
}

// =============== Kernel 0: one-shot W -> B-fragment conversion =============
// word index w = ((split*64 + nt*8 + s)*32 + ln)*2 + reg
// B fragment (m16n8k16.row.col): b0={B[2t][g],B[2t+1][g]}, b1 = k+8; g=ln>>2,
// t=ln&3, B[k][n] = W[n][k].
__global__ void __launch_bounds__(128) prep_bfrag(
    const float* __restrict__ Wf, const float* __restrict__ Wi,
    const float* __restrict__ Wg, const float* __restrict__ Wo)
{
    int w = blockIdx.x * 128 + threadIdx.x;
    int split = w >> 12;
    int nt = (w >> 9) & 7, s = (w >> 6) & 7;
    int ln = (w >> 1) & 31, reg = w & 1;
    int n = nt * 8 + (ln >> 2);
    int k0 = s * 16 + (ln & 3) * 2 + reg * 8;
    const float* wr = ((n < 16) ? Wf : (n < 32) ? Wi : (n < 48) ? Wg : Wo)
                      + (n & 15) * 144 + k0;
    float v0 = wr[0], v1 = wr[1];
    __nv_bfloat16 h0 = __float2bfloat16_rn(v0);
    __nv_bfloat16 h1 = __float2bfloat16_rn(v1);
    uint32_t outw;
    if (split == 0) {
        outw = pack_bf2(h0, h1);
    } else {
        __nv_bfloat16 l0 = __float2bfloat16_rn(v0 - __bfloat162float(h0));
        __nv_bfloat16 l1 = __float2bfloat16_rn(v1 - __bfloat162float(h1));
        outw = pack_bf2(l0, l1);
    }
    g_bfrag[w] = outw;
}

// =================== Kernel 1: mma.sync split-bf16 GEMM ====================
// C[row][n] = bias[n] + sum_{k<128} x[row][k]*W[n][k].  Split x=xh+xl, W=wh+wl;
// C = xh*wh + xh*wl + xl*wh (fp32 accum; dropped xl*wl ~ 2^-18).
// A lives in smem as plain row-major bf16 planes (hi, lo), 256B rows, 16B-chunk
// XOR swizzle (chunk ^= row&7); fragments loaded with ldmatrix.x4 (canonical
// m16n8k16 A mapping: t0-7 rows 0-7 k0, t8-15 rows 8-15 k0, t16-23 rows 0-7
// k+8, t24-31 rows 8-15 k+8).
// CTA = 128 threads (4 warps). Warp tile M=32 (2 m-tiles) x N=64 x K=128.
#define SM_BIAS 0
#define SM_BF   256                       // B frags copied from g_bfrag (32KB)
#define SM_A    (256 + 32768)             // A planes: 2 x 128 rows x 256B = 64KB
#define SM_TOT  (SM_A + 65536)            // 98560 B

__global__ void __launch_bounds__(128) proj_mma(
    const float* __restrict__ x,
    const float* __restrict__ bf_, const float* __restrict__ bi_,
    const float* __restrict__ bg_, const float* __restrict__ bo_)
{
    extern __shared__ char smem[];
    uint32_t sbase = (uint32_t)__cvta_generic_to_shared(smem);
    int tid = threadIdx.x, warp = tid >> 5, lane = tid & 31;

    // ---- bias -> smem ----
    if (tid < 64) {
        const float* bp = (tid < 16) ? bf_ : (tid < 32) ? bi_
                        : (tid < 48) ? bg_ : bo_;
        ((float*)(smem + SM_BIAS))[tid] = bp[tid & 15];
    }

    // ---- B fragments: coalesced copy from g_bfrag (L2-resident 32KB) ----
#pragma unroll
    for (int i = 0; i < 16; i++)
        ((uint4*)(smem + SM_BF))[tid + 128 * i] =
            ((const uint4*)g_bfrag)[tid + 128 * i];

    // ---- A: convert rows to bf16 hi/lo planes, coalesced STS.64 ----
    size_t rowbase = (size_t)blockIdx.x * 128 + warp * 32;
    {
#pragma unroll 4
        for (int i = 0; i < 32; i++) {
            float4 v = ((const float4*)x)[(rowbase + i) * 32 + lane];
            int R = warp * 32 + i;
            uint32_t addr = (uint32_t)(SM_A + R * 256 +
                ((((lane >> 1) ^ (R & 7)) << 4) + (lane & 1) * 8));
            uint32_t hi01 = cvt_pair(v.y, v.x);
            uint32_t hi23 = cvt_pair(v.w, v.z);
            float h0 = __uint_as_float(hi01 << 16);
            float h1 = __uint_as_float(hi01 & 0xffff0000u);
            float h2 = __uint_as_float(hi23 << 16);
            float h3 = __uint_as_float(hi23 & 0xffff0000u);
            uint32_t lo01 = cvt_pair(v.y - h1, v.x - h0);
            uint32_t lo23 = cvt_pair(v.w - h3, v.z - h2);
            *(uint2*)(smem + addr) = make_uint2(hi01, hi23);
            *(uint2*)(smem + addr + 32768) = make_uint2(lo01, lo23);
        }
    }
    __syncthreads();

    // ---- mainloop ----
    float acc[2][8][4];
#pragma unroll
    for (int mt = 0; mt < 2; mt++)
#pragma unroll
        for (int nt = 0; nt < 8; nt++)
#pragma unroll
            for (int r = 0; r < 4; r++) acc[mt][nt][r] = 0.f;

    int a_row = warp * 32 + (lane & 15);     // + mt*16
    int a_hi8 = lane >> 4;                   // col +8 selector

#pragma unroll 1
    for (int s = 0; s < 8; s++) {
        // A fragments via ldmatrix.x4: [split][mt] -> 4 regs each
        uint32_t af[2][2][4];
#pragma unroll
        for (int split = 0; split < 2; split++) {
#pragma unroll
            for (int mt = 0; mt < 2; mt++) {
                int R = a_row + mt * 16;
                uint32_t addr = sbase + SM_A + split * 32768 + R * 256 +
                                (((s * 2 + a_hi8) ^ (R & 7)) << 4);
                asm volatile(
                    "ldmatrix.sync.aligned.m8n8.x4.shared.b16 "
                    "{%0,%1,%2,%3}, [%4];"
                    : "=r"(af[split][mt][0]), "=r"(af[split][mt][1]),
                      "=r"(af[split][mt][2]), "=r"(af[split][mt][3])
                    : "r"(addr));
            }
        }
#pragma unroll
        for (int nt = 0; nt < 8; nt++) {
            uint2 b0 = *(const uint2*)(smem + SM_BF +
                ((((0 * 64 + nt * 8 + s) * 32) + lane) << 3));
            uint2 b1 = *(const uint2*)(smem + SM_BF +
                ((((1 * 64 + nt * 8 + s) * 32) + lane) << 3));
#pragma unroll
            for (int mt = 0; mt < 2; mt++) {
#define MMA(A, BX, BY)                                                       \
    asm volatile(                                                            \
        "mma.sync.aligned.m16n8k16.row.col.f32.bf16.bf16.f32 "               \
        "{%0,%1,%2,%3}, {%4,%5,%6,%7}, {%8,%9}, {%0,%1,%2,%3};"              \
        : "+f"(acc[mt][nt][0]), "+f"(acc[mt][nt][1]),                        \
          "+f"(acc[mt][nt][2]), "+f"(acc[mt][nt][3])                         \
        : "r"((A)[0]), "r"((A)[1]), "r"((A)[2]), "r"((A)[3]),                \
          "r"(BX), "r"(BY))
                MMA(af[0][mt], b0.x, b0.y);   // xh*wh
                MMA(af[0][mt], b1.x, b1.y);   // xh*wl
                MMA(af[1][mt], b0.x, b0.y);   // xl*wh
#undef MMA
            }
        }
    }

    // ---- epilogue: + bias, store f32 pairs ----
    int g = lane >> 2, t = lane & 3;
#pragma unroll
    for (int mt = 0; mt < 2; mt++) {
#pragma unroll
        for (int nt = 0; nt < 8; nt++) {
            int col = nt * 8 + t * 2;
            float2 bb = *(const float2*)(smem + SM_BIAS + col * 4);
            size_t r0 = rowbase + mt * 16 + g;
            float2 o0, o1;
            o0.x = acc[mt][nt][0] + bb.x;
            o0.y = acc[mt][nt][1] + bb.y;
            o1.x = acc[mt][nt][2] + bb.x;
            o1.y = acc[mt][nt][3] + bb.y;
            *(float2*)(g_proj + r0 * 64 + col) = o0;
            *(float2*)(g_proj + (r0 + 8) * 64 + col) = o1;
        }
    }
}

// ---------------- fast activations ----------------
__device__ __forceinline__ float fsigmoid(float x) {
    return __fdividef(1.f, 1.f + __expf(-x));
}
__device__ __forceinline__ float ftanh(float x) {
    float e = __expf(-2.f * x);
    return __fdividef(1.f - e, 1.f + e);
}
// Predicated store: no BSSY/BSYNC divergence region.
__device__ __forceinline__ void st_pred(float* p, float v, int pred) {
    asm volatile("{\n\t.reg .pred p;\n\tsetp.ne.s32 p, %2, 0;\n\t"
                 "@p st.global.f32 [%0], %1;\n\t}"
                 :: "l"(p), "f"(v), "r"(pred) : "memory");
}

// ============= Kernel 2: recurrence, ILP-2 + depth-4 prefetch ==============
// Each warp runs TWO independent batch elements (b0, b0+512): the two serial
// chains interleave in one instruction stream, covering shfl/MUFU/FMA latency.
// Lane l: j=l&15 hidden unit, half=l>>4; half0 owns (f,i), half1 owns (g,o).
__global__ void __launch_bounds__(128) recur(
    const float* __restrict__ Wf, const float* __restrict__ Wi,
    const float* __restrict__ Wg, const float* __restrict__ Wo,
    const float* __restrict__ thf, const float* __restrict__ thi,
    const float* __restrict__ thg, const float* __restrict__ tho,
    float* __restrict__ out)
{
    int wid = threadIdx.x >> 5;
    int b0 = blockIdx.x * 4 + wid;      // 0..511
    int l = threadIdx.x & 31;
    int j = l & 15;
    int half = l >> 4;
    int seg = l & 16;
    const unsigned FULL = 0xffffffffu;

    const float* WA = half ? Wg : Wf;
    const float* WB = half ? Wo : Wi;
    float tA = (half ? thg : thf)[j];
    float tB = (half ? tho : thi)[j];

    float wrA[16], wrB[16];          // shared by both batches
#pragma unroll
    for (int k = 0; k < 16; k++) {
        wrA[k] = WA[j * 144 + 128 + k];
        wrB[k] = WB[j * 144 + 128 + k];
    }

    float h[2] = {0.f, 0.f}, c[2] = {0.f, 0.f};
    const float* pp[2];
    pp[0] = g_proj + (size_t)b0 * 64 + half * 32 + j;
    pp[1] = g_proj + (size_t)(b0 + 512) * 64 + half * 32 + j;
    float* op[2];
    op[0] = out + (b0 << 4) + j;
    op[1] = out + ((b0 + 512) << 4) + j;
    int store_h = (half == 0);

    float curA[2][4], curB[2][4];
#pragma unroll
    for (int bi = 0; bi < 2; bi++)
#pragma unroll
        for (int u = 0; u < 4; u++) {
            curA[bi][u] = pp[bi][(size_t)u * STRIDE];
            curB[bi][u] = pp[bi][(size_t)u * STRIDE + 16];
        }

    for (int g = 0; g < T_STEPS / 4; g++) {
        float nA[2][4], nB[2][4];
#pragma unroll
        for (int bi = 0; bi < 2; bi++)
#pragma unroll
            for (int u = 0; u < 4; u++) {
                nA[bi][u] = pp[bi][(size_t)(4 + u) * STRIDE];
                nB[bi][u] = pp[bi][(size_t)(4 + u) * STRIDE + 16];
            }

#pragma unroll
        for (int u = 0; u < 4; u++) {
            // ---- matvec (both batches, interleaved) ----
            float sA[2][4], sB[2][4];
#pragma unroll
            for (int bi = 0; bi < 2; bi++)
#pragma unroll
                for (int r = 0; r < 4; r++) { sA[bi][r] = 0.f; sB[bi][r] = 0.f; }
#pragma unroll
            for (int k = 0; k < 16; k += 4) {
                float hk[2][4];
#pragma unroll
                for (int bi = 0; bi < 2; bi++) {
                    hk[bi][0] = __shfl_sync(FULL, h[bi], seg + k + 0);
                    hk[bi][1] = __shfl_sync(FULL, h[bi], seg + k + 1);
                    hk[bi][2] = __shfl_sync(FULL, h[bi], seg + k + 2);
                    hk[bi][3] = __shfl_sync(FULL, h[bi], seg + k + 3);
                }
#pragma unroll
                for (int bi = 0; bi < 2; bi++)
#pragma unroll
                    for (int r = 0; r < 4; r++) {
                        sA[bi][r] = fmaf(hk[bi][r], wrA[k + r], sA[bi][r]);
                        sB[bi][r] = fmaf(hk[bi][r], wrB[k + r], sB[bi][r]);
                    }
            }
            float aA[2], aB[2];
#pragma unroll
            for (int bi = 0; bi < 2; bi++) {
                aA[bi] = curA[bi][u] +
                         ((sA[bi][0] + sA[bi][1]) + (sA[bi][2] + sA[bi][3]));
                aB[bi] = curB[bi][u] +
                         ((sB[bi][0] + sB[bi][1]) + (sB[bi][2] + sB[bi][3]));
            }

            // ---- qgate: sin + 16-lane inclusive scan ----
            float snA[2], snB[2], cA[2], cB[2];
#pragma unroll
            for (int bi = 0; bi < 2; bi++) {
                snA[bi] = __sinf(aA[bi] + tA);
                snB[bi] = __sinf(aB[bi] + tB);
                cA[bi] = snA[bi]; cB[bi] = snB[bi];
            }
#pragma unroll
            for (int off = 1; off < 16; off <<= 1) {
                float uA[2], uB[2];
#pragma unroll
                for (int bi = 0; bi < 2; bi++) {
                    uA[bi] = __shfl_up_sync(FULL, cA[bi], off, 16);
                    uB[bi] = __shfl_up_sync(FULL, cB[bi], off, 16);
                }
#pragma unroll
                for (int bi = 0; bi < 2; bi++) {
                    cA[bi] += (j >= off) ? uA[bi] : 0.f;
                    cB[bi] += (j >= off) ? uB[bi] : 0.f;
                }
            }
            float qA[2], qB[2];
#pragma unroll
            for (int bi = 0; bi < 2; bi++) {
                float ttA = __shfl_sync(FULL, cA[bi], seg + 15);
                float ttB = __shfl_sync(FULL, cB[bi], seg + 15);
                qA[bi] = (j == 0) ? (snA[bi] + ttA) : cA[bi];
                qB[bi] = (j == 0) ? (snB[bi] + ttB) : cB[bi];
            }

            // ---- activations + cross-half exchange + state update ----
            float vA[2], vB[2];
#pragma unroll
            for (int bi = 0; bi < 2; bi++) {
                float eA = __expf(half ? (-2.f * qA[bi]) : (-qA[bi]));
                vA[bi] = __fdividef(half ? (1.f - eA) : 1.f, 1.f + eA);
                vB[bi] = fsigmoid(qB[bi]);
            }
#pragma unroll
            for (int bi = 0; bi < 2; bi++) {
                float oA = __shfl_xor_sync(FULL, vA[bi], 16);
                float oB = __shfl_xor_sync(FULL, vB[bi], 16);
                float f_ = half ? oA : vA[bi];
                float i_ = half ? oB : vB[bi];
                float g_ = half ? vA[bi] : oA;
                float o_ = half ? vB[bi] : oB;
                c[bi] = f_ * c[bi] + i_ * g_;
                h[bi] = o_ * ftanh(c[bi]);
            }

            st_pred(op[0], h[0], store_h);
            st_pred(op[1], h[1], store_h);
            op[0] += BATCH * HID;
            op[1] += BATCH * HID;
        }

#pragma unroll
        for (int bi = 0; bi < 2; bi++) {
#pragma unroll
            for (int u = 0; u < 4; u++) {
                curA[bi][u] = nA[bi][u];
                curB[bi][u] = nB[bi][u];
            }
            pp[bi] += (size_t)4 * STRIDE;
        }
    }

    size_t base = (size_t)T_STEPS * BATCH * HID;
    st_pred(out + base + (b0 << 4) + j, h[0], store_h);
    st_pred(out + base + BATCH * HID + (b0 << 4) + j, c[0], store_h);
    st_pred(out + base + ((b0 + 512) << 4) + j, h[1], store_h);
    st_pred(out + base + BATCH * HID + ((b0 + 512) << 4) + j, c[1], store_h);
}

// ---------------- launch ----------------
extern "C" void kernel_launch(void* const* d_in, const int* in_sizes, int n_in,
                              void* d_out, int out_size) {
    const float* x   = (const float*)d_in[0];
    const float* Wf  = (const float*)d_in[1];
    const float* bf_ = (const float*)d_in[2];
    const float* thf = (const float*)d_in[3];
    const float* Wi  = (const float*)d_in[4];
    const float* bi_ = (const float*)d_in[5];
    const float* thi = (const float*)d_in[6];
    const float* Wg  = (const float*)d_in[7];
    const float* bg_ = (const float*)d_in[8];
    const float* thg = (const float*)d_in[9];
    const float* Wo  = (const float*)d_in[10];
    const float* bo_ = (const float*)d_in[11];
    const float* tho = (const float*)d_in[12];
    float* out = (float*)d_out;

    cudaFuncSetAttribute(proj_mma,
                         cudaFuncAttributeMaxDynamicSharedMemorySize, SM_TOT);

    prep_bfrag<<<64, 128>>>(Wf, Wi, Wg, Wo);
    proj_mma<<<NROWS / 128, 128, SM_TOT>>>(x, bf_, bi_, bg_, bo_);
    recur<<<128, 128>>>(Wf, Wi, Wg, Wo, thf, thi, thg, tho, out);
}

// round 13
// speedup vs baseline: 2.6318x; 1.2262x over previous
#include <cuda_runtime.h>
#include <cuda_bf16.h>
#include <cstdint>

#define T_STEPS 1024
#define BATCH   1024
#define INDIM   128
#define HID     16
#define NROWS   (T_STEPS * BATCH)
#define STRIDE  (BATCH * 64)          // floats per timestep in g_proj

#define RECUR_BLOCKS 128
#define PROJ_BLOCKS  (NROWS / 128)    // 8192
#define PASS_T       16               // timesteps per pass
#define NPASS        (T_STEPS / PASS_T)        // 64
#define BLKS_PER_PASS (PROJ_BLOCKS / NPASS)    // 128

// Scratch: per-(t,b) input projections, 4 gates x 16 hidden = 64 floats/row.
// Layout: g_proj[row*64 + gate*16 + n], row = t*BATCH + b.
// Padded by 4 timesteps for the depth-4 prefetch in the recurrence.
__device__ float g_proj[(size_t)(NROWS + 4 * BATCH) * 64];
// Pre-packed B (weight) mma fragments: 2 splits x 8 nt x 8 s x 32 lanes x 2 regs.
__device__ uint32_t g_bfrag[8192];
// Per-pass producer completion counters (memset to 0 each launch).
__device__ int g_cnt[NPASS];

__device__ __forceinline__ uint32_t pack_bf2(__nv_bfloat16 lo, __nv_bfloat16 hi) {
    return ((uint32_t)__bfloat16_as_ushort(hi) << 16) | __bfloat16_as_ushort(lo);
}
// packed = { lo16 = bf16(losrc), hi16 = bf16(hisrc) }
__device__ __forceinline__ uint32_t cvt_pair(float hisrc, float losrc) {
    uint32_t r;
    asm("cvt.rn.bf16x2.f32 %0, %1, %2;" : "=r"(r) : "f"(hisrc), "f"(losrc));
    return r;
}
__device__ __forceinline__ int ld_acq(const int* p) {
    int v;
    asm volatile("ld.acquire.gpu.global.b32 %0, [%1];" : "=r"(v) : "l"(p) : "memory");
    return v;
}
__device__ __forceinline__ void wait_pass(int p) {
    const int* a = &g_cnt[p];
    while (ld_acq(a) < BLKS_PER_PASS) __nanosleep(128);
}

// =============== Kernel 0: one-shot W -> B-fragment conversion =============
// word index w = ((split*64 + nt*8 + s)*32 + ln)*2 + reg
// B fragment (m16n8k16.row.col): b0={B[2t][g],B[2t+1][g]}, b1 = k+8; g=ln>>2,
// t=ln&3, B[k][n] = W[n][k].
__global__ void __launch_bounds__(128) prep_bfrag(
    const float* __restrict__ Wf, const float* __restrict__ Wi,
    const float* __restrict__ Wg, const float* __restrict__ Wo)
{
    int w = blockIdx.x * 128 + threadIdx.x;
    int split = w >> 12;
    int nt = (w >> 9) & 7, s = (w >> 6) & 7;
    int ln = (w >> 1) & 31, reg = w & 1;
    int n = nt * 8 + (ln >> 2);
    int k0 = s * 16 + (ln & 3) * 2 + reg * 8;
    const float* wr = ((n < 16) ? Wf : (n < 32) ? Wi : (n < 48) ? Wg : Wo)
                      + (n & 15) * 144 + k0;
    float v0 = wr[0], v1 = wr[1];
    __nv_bfloat16 h0 = __float2bfloat16_rn(v0);
    __nv_bfloat16 h1 = __float2bfloat16_rn(v1);
    uint32_t outw;
    if (split == 0) {
        outw = pack_bf2(h0, h1);
    } else {
        __nv_bfloat16 l0 = __float2bfloat16_rn(v0 - __bfloat162float(h0));
        __nv_bfloat16 l1 = __float2bfloat16_rn(v1 - __bfloat162float(h1));
        outw = pack_bf2(l0, l1);
    }
    g_bfrag[w] = outw;
}

// ---------------- fast activations ----------------
__device__ __forceinline__ float fsigmoid(float x) {
    return __fdividef(1.f, 1.f + __expf(-x));
}
__device__ __forceinline__ float ftanh(float x) {
    float e = __expf(-2.f * x);
    return __fdividef(1.f - e, 1.f + e);
}
// Predicated store: no BSSY/BSYNC divergence region.
__device__ __forceinline__ void st_pred(float* p, float v, int pred) {
    asm volatile("{\n\t.reg .pred p;\n\tsetp.ne.s32 p, %2, 0;\n\t"
                 "@p st.global.f32 [%0], %1;\n\t}"
                 :: "l"(p), "f"(v), "r"(pred) : "memory");
}

// ================== fused kernel: role by blockIdx.x =======================
// blocks [0,128): recurrence (all resident in wave 1; consumers).
// blocks [128, 128+8192): mma.sync split-bf16 GEMM (producers, streamed).
#define SM_BIAS 0
#define SM_BF   256                       // B frags copied from g_bfrag (32KB)
#define SM_A    (256 + 32768)             // A planes: 2 x 128 rows x 256B = 64KB
#define SM_TOT  (SM_A + 65536)            // 98560 B

__global__ void __launch_bounds__(128) fused(
    const float* __restrict__ x,
    const float* __restrict__ Wf, const float* __restrict__ bf_,
    const float* __restrict__ thf,
    const float* __restrict__ Wi, const float* __restrict__ bi_,
    const float* __restrict__ thi,
    const float* __restrict__ Wg, const float* __restrict__ bg_,
    const float* __restrict__ thg,
    const float* __restrict__ Wo, const float* __restrict__ bo_,
    const float* __restrict__ tho,
    float* __restrict__ out)
{
    extern __shared__ char smem[];
    int tid = threadIdx.x, warp = tid >> 5, lane = tid & 31;

    if (blockIdx.x >= RECUR_BLOCKS) {
        // ===================== producer: MMA GEMM ==========================
        int pbid = blockIdx.x - RECUR_BLOCKS;
        uint32_t sbase = (uint32_t)__cvta_generic_to_shared(smem);

        // bias -> smem
        if (tid < 64) {
            const float* bp = (tid < 16) ? bf_ : (tid < 32) ? bi_
                            : (tid < 48) ? bg_ : bo_;
            ((float*)(smem + SM_BIAS))[tid] = bp[tid & 15];
        }
        // B fragments: coalesced copy from g_bfrag (L2-resident 32KB)
#pragma unroll
        for (int i = 0; i < 16; i++)
            ((uint4*)(smem + SM_BF))[tid + 128 * i] =
                ((const uint4*)g_bfrag)[tid + 128 * i];

        // A: convert rows to bf16 hi/lo planes, coalesced STS.64
        size_t rowbase = (size_t)pbid * 128 + warp * 32;
        {
#pragma unroll 4
            for (int i = 0; i < 32; i++) {
                float4 v = ((const float4*)x)[(rowbase + i) * 32 + lane];
                int R = warp * 32 + i;
                uint32_t addr = (uint32_t)(SM_A + R * 256 +
                    ((((lane >> 1) ^ (R & 7)) << 4) + (lane & 1) * 8));
                uint32_t hi01 = cvt_pair(v.y, v.x);
                uint32_t hi23 = cvt_pair(v.w, v.z);
                float h0 = __uint_as_float(hi01 << 16);
                float h1 = __uint_as_float(hi01 & 0xffff0000u);
                float h2 = __uint_as_float(hi23 << 16);
                float h3 = __uint_as_float(hi23 & 0xffff0000u);
                uint32_t lo01 = cvt_pair(v.y - h1, v.x - h0);
                uint32_t lo23 = cvt_pair(v.w - h3, v.z - h2);
                *(uint2*)(smem + addr) = make_uint2(hi01, hi23);
                *(uint2*)(smem + addr + 32768) = make_uint2(lo01, lo23);
            }
        }
        __syncthreads();

        float acc[2][8][4];
#pragma unroll
        for (int mt = 0; mt < 2; mt++)
#pragma unroll
            for (int nt = 0; nt < 8; nt++)
#pragma unroll
                for (int r = 0; r < 4; r++) acc[mt][nt][r] = 0.f;

        int a_row = warp * 32 + (lane & 15);
        int a_hi8 = lane >> 4;

#pragma unroll 1
        for (int s = 0; s < 8; s++) {
            uint32_t af[2][2][4];
#pragma unroll
            for (int split = 0; split < 2; split++) {
#pragma unroll
                for (int mt = 0; mt < 2; mt++) {
                    int R = a_row + mt * 16;
                    uint32_t addr = sbase + SM_A + split * 32768 + R * 256 +
                                    (((s * 2 + a_hi8) ^ (R & 7)) << 4);
                    asm volatile(
                        "ldmatrix.sync.aligned.m8n8.x4.shared.b16 "
                        "{%0,%1,%2,%3}, [%4];"
                        : "=r"(af[split][mt][0]), "=r"(af[split][mt][1]),
                          "=r"(af[split][mt][2]), "=r"(af[split][mt][3])
                        : "r"(addr));
                }
            }
#pragma unroll
            for (int nt = 0; nt < 8; nt++) {
                uint2 b0 = *(const uint2*)(smem + SM_BF +
                    ((((0 * 64 + nt * 8 + s) * 32) + lane) << 3));
                uint2 b1 = *(const uint2*)(smem + SM_BF +
                    ((((1 * 64 + nt * 8 + s) * 32) + lane) << 3));
#pragma unroll
                for (int mt = 0; mt < 2; mt++) {
#define MMA(A, BX, BY)                                                       \
    asm volatile(                                                            \
        "mma.sync.aligned.m16n8k16.row.col.f32.bf16.bf16.f32 "               \
        "{%0,%1,%2,%3}, {%4,%5,%6,%7}, {%8,%9}, {%0,%1,%2,%3};"              \
        : "+f"(acc[mt][nt][0]), "+f"(acc[mt][nt][1]),                        \
          "+f"(acc[mt][nt][2]), "+f"(acc[mt][nt][3])                         \
        : "r"((A)[0]), "r"((A)[1]), "r"((A)[2]), "r"((A)[3]),                \
          "r"(BX), "r"(BY))
                    MMA(af[0][mt], b0.x, b0.y);   // xh*wh
                    MMA(af[0][mt], b1.x, b1.y);   // xh*wl
                    MMA(af[1][mt], b0.x, b0.y);   // xl*wh
#undef MMA
                }
            }
        }

        // epilogue: + bias, store f32 pairs
        int g = lane >> 2, t = lane & 3;
#pragma unroll
        for (int mt = 0; mt < 2; mt++) {
#pragma unroll
            for (int nt = 0; nt < 8; nt++) {
                int col = nt * 8 + t * 2;
                float2 bb = *(const float2*)(smem + SM_BIAS + col * 4);
                size_t r0 = rowbase + mt * 16 + g;
                float2 o0, o1;
                o0.x = acc[mt][nt][0] + bb.x;
                o0.y = acc[mt][nt][1] + bb.y;
                o1.x = acc[mt][nt][2] + bb.x;
                o1.y = acc[mt][nt][3] + bb.y;
                *(float2*)(g_proj + r0 * 64 + col) = o0;
                *(float2*)(g_proj + (r0 + 8) * 64 + col) = o1;
            }
        }

        // release: all stores visible, then count this block into its pass
        __threadfence();
        __syncthreads();
        if (tid == 0) atomicAdd(&g_cnt[pbid >> 7], 1);
        return;
    }

    // ==================== consumer: recurrence (ILP-2) =====================
    // Each warp runs TWO independent batch elements (b0, b0+512).
    // Lane l: j=l&15 hidden unit, half=l>>4; half0 owns (f,i), half1 (g,o).
    int wid = warp;
    int b0 = blockIdx.x * 4 + wid;      // 0..511
    int l = tid & 31;
    int j = l & 15;
    int half = l >> 4;
    int seg = l & 16;
    const unsigned FULL = 0xffffffffu;

    const float* WA = half ? Wg : Wf;
    const float* WB = half ? Wo : Wi;
    float tA = (half ? thg : thf)[j];
    float tB = (half ? tho : thi)[j];

    float wrA[16], wrB[16];          // shared by both batches
#pragma unroll
    for (int k = 0; k < 16; k++) {
        wrA[k] = WA[j * 144 + 128 + k];
        wrB[k] = WB[j * 144 + 128 + k];
    }

    float h[2] = {0.f, 0.f}, c[2] = {0.f, 0.f};
    const float* pp[2];
    pp[0] = g_proj + (size_t)b0 * 64 + half * 32 + j;
    pp[1] = g_proj + (size_t)(b0 + 512) * 64 + half * 32 + j;
    float* op[2];
    op[0] = out + (b0 << 4) + j;
    op[1] = out + ((b0 + 512) << 4) + j;
    int store_h = (half == 0);

    // Wait for pass 0 before preloading steps 0..3.
    wait_pass(0);
    float curA[2][4], curB[2][4];
#pragma unroll
    for (int bi = 0; bi < 2; bi++)
#pragma unroll
        for (int u = 0; u < 4; u++) {
            curA[bi][u] = pp[bi][(size_t)u * STRIDE];
            curB[bi][u] = pp[bi][(size_t)u * STRIDE + 16];
        }

    for (int g = 0; g < T_STEPS / 4; g++) {
        // Next prefetch group belongs to pass (g+1)>>2 (groups never straddle
        // a pass: 16 steps/pass = 4 groups). Wait at pass entry.
        if (((g + 1) & 3) == 0 && ((g + 1) >> 2) < NPASS)
            wait_pass((g + 1) >> 2);

        float nA[2][4], nB[2][4];
#pragma unroll
        for (int bi = 0; bi < 2; bi++)
#pragma unroll
            for (int u = 0; u < 4; u++) {
                nA[bi][u] = pp[bi][(size_t)(4 + u) * STRIDE];
                nB[bi][u] = pp[bi][(size_t)(4 + u) * STRIDE + 16];
            }

#pragma unroll
        for (int u = 0; u < 4; u++) {
            // ---- matvec (both batches, interleaved) ----
            float sA[2][4], sB[2][4];
#pragma unroll
            for (int bi = 0; bi < 2; bi++)
#pragma unroll
                for (int r = 0; r < 4; r++) { sA[bi][r] = 0.f; sB[bi][r] = 0.f; }
#pragma unroll
            for (int k = 0; k < 16; k += 4) {
                float hk[2][4];
#pragma unroll
                for (int bi = 0; bi < 2; bi++) {
                    hk[bi][0] = __shfl_sync(FULL, h[bi], seg + k + 0);
                    hk[bi][1] = __shfl_sync(FULL, h[bi], seg + k + 1);
                    hk[bi][2] = __shfl_sync(FULL, h[bi], seg + k + 2);
                    hk[bi][3] = __shfl_sync(FULL, h[bi], seg + k + 3);
                }
#pragma unroll
                for (int bi = 0; bi < 2; bi++)
#pragma unroll
                    for (int r = 0; r < 4; r++) {
                        sA[bi][r] = fmaf(hk[bi][r], wrA[k + r], sA[bi][r]);
                        sB[bi][r] = fmaf(hk[bi][r], wrB[k + r], sB[bi][r]);
                    }
            }
            float aA[2], aB[2];
#pragma unroll
            for (int bi = 0; bi < 2; bi++) {
                aA[bi] = curA[bi][u] +
                         ((sA[bi][0] + sA[bi][1]) + (sA[bi][2] + sA[bi][3]));
                aB[bi] = curB[bi][u] +
                         ((sB[bi][0] + sB[bi][1]) + (sB[bi][2] + sB[bi][3]));
            }

            // ---- qgate: sin + 16-lane inclusive scan ----
            float snA[2], snB[2], cA[2], cB[2];
#pragma unroll
            for (int bi = 0; bi < 2; bi++) {
                snA[bi] = __sinf(aA[bi] + tA);
                snB[bi] = __sinf(aB[bi] + tB);
                cA[bi] = snA[bi]; cB[bi] = snB[bi];
            }
#pragma unroll
            for (int off = 1; off < 16; off <<= 1) {
                float uA[2], uB[2];
#pragma unroll
                for (int bi = 0; bi < 2; bi++) {
                    uA[bi] = __shfl_up_sync(FULL, cA[bi], off, 16);
                    uB[bi] = __shfl_up_sync(FULL, cB[bi], off, 16);
                }
#pragma unroll
                for (int bi = 0; bi < 2; bi++) {
                    cA[bi] += (j >= off) ? uA[bi] : 0.f;
                    cB[bi] += (j >= off) ? uB[bi] : 0.f;
                }
            }
            float qA[2], qB[2];
#pragma unroll
            for (int bi = 0; bi < 2; bi++) {
                float ttA = __shfl_sync(FULL, cA[bi], seg + 15);
                float ttB = __shfl_sync(FULL, cB[bi], seg + 15);
                qA[bi] = (j == 0) ? (snA[bi] + ttA) : cA[bi];
                qB[bi] = (j == 0) ? (snB[bi] + ttB) : cB[bi];
            }

            // ---- activations + cross-half exchange + state update ----
            float vA[2], vB[2];
#pragma unroll
            for (int bi = 0; bi < 2; bi++) {
                float eA = __expf(half ? (-2.f * qA[bi]) : (-qA[bi]));
                vA[bi] = __fdividef(half ? (1.f - eA) : 1.f, 1.f + eA);
                vB[bi] = fsigmoid(qB[bi]);
            }
#pragma unroll
            for (int bi = 0; bi < 2; bi++) {
                float oA = __shfl_xor_sync(FULL, vA[bi], 16);
                float oB = __shfl_xor_sync(FULL, vB[bi], 16);
                float f_ = half ? oA : vA[bi];
                float i_ = half ? oB : vB[bi];
                float g_ = half ? vA[bi] : oA;
                float o_ = half ? vB[bi] : oB;
                c[bi] = f_ * c[bi] + i_ * g_;
                h[bi] = o_ * ftanh(c[bi]);
            }

            st_pred(op[0], h[0], store_h);
            st_pred(op[1], h[1], store_h);
            op[0] += BATCH * HID;
            op[1] += BATCH * HID;
        }

#pragma unroll
        for (int bi = 0; bi < 2; bi++) {
#pragma unroll
            for (int u = 0; u < 4; u++) {
                curA[bi][u] = nA[bi][u];
                curB[bi][u] = nB[bi][u];
            }
            pp[bi] += (size_t)4 * STRIDE;
        }
    }

    size_t base = (size_t)T_STEPS * BATCH * HID;
    st_pred(out + base + (b0 << 4) + j, h[0], store_h);
    st_pred(out + base + BATCH * HID + (b0 << 4) + j, c[0], store_h);
    st_pred(out + base + ((b0 + 512) << 4) + j, h[1], store_h);
    st_pred(out + base + BATCH * HID + ((b0 + 512) << 4) + j, c[1], store_h);
}

// ---------------- launch ----------------
extern "C" void kernel_launch(void* const* d_in, const int* in_sizes, int n_in,
                              void* d_out, int out_size) {
    const float* x   = (const float*)d_in[0];
    const float* Wf  = (const float*)d_in[1];
    const float* bf_ = (const float*)d_in[2];
    const float* thf = (const float*)d_in[3];
    const float* Wi  = (const float*)d_in[4];
    const float* bi_ = (const float*)d_in[5];
    const float* thi = (const float*)d_in[6];
    const float* Wg  = (const float*)d_in[7];
    const float* bg_ = (const float*)d_in[8];
    const float* thg = (const float*)d_in[9];
    const float* Wo  = (const float*)d_in[10];
    const float* bo_ = (const float*)d_in[11];
    const float* tho = (const float*)d_in[12];
    float* out = (float*)d_out;

    cudaFuncSetAttribute(fused,
                         cudaFuncAttributeMaxDynamicSharedMemorySize, SM_TOT);

    // Reset pass counters (graph-capturable async memset; no allocation).
    void* cnt_addr = nullptr;
    cudaGetSymbolAddress(&cnt_addr, g_cnt);
    cudaMemsetAsync(cnt_addr, 0, sizeof(int) * NPASS);

    prep_bfrag<<<64, 128>>>(Wf, Wi, Wg, Wo);
    fused<<<RECUR_BLOCKS + PROJ_BLOCKS, 128, SM_TOT>>>(
        x, Wf, bf_, thf, Wi, bi_, thi, Wg, bg_, thg, Wo, bo_, tho, out);
}

// round 15
// speedup vs baseline: 3.0199x; 1.1474x over previous
#include <cuda_runtime.h>
#include <cuda_bf16.h>
#include <cstdint>

#define T_STEPS 1024
#define BATCH   1024
#define INDIM   128
#define HID     16
#define NROWS   (T_STEPS * BATCH)
#define STRIDE  (BATCH * 64)          // floats per timestep in g_proj

#define RECUR_BLOCKS 128
#define ROWS_PER_PBLK 256
#define PROJ_BLOCKS  (NROWS / ROWS_PER_PBLK)   // 4096
#define PASS_T       16                        // timesteps per pass
#define NPASS        (T_STEPS / PASS_T)        // 64
#define BLKS_PER_PASS (PROJ_BLOCKS / NPASS)    // 64

// Scratch: per-(t,b) input projections, 4 gates x 16 hidden = 64 floats/row.
// Layout: g_proj[row*64 + gate*16 + n], row = t*BATCH + b.
// Padded by 4 timesteps for the depth-4 prefetch in the recurrence.
__device__ float g_proj[(size_t)(NROWS + 4 * BATCH) * 64];
// Pre-packed B (weight) mma fragments: 2 splits x 8 nt x 8 s x 32 lanes x 2 regs.
__device__ uint32_t g_bfrag[8192];
// Per-pass producer completion counters (memset to 0 each launch).
__device__ int g_cnt[NPASS];

__device__ __forceinline__ uint32_t pack_bf2(__nv_bfloat16 lo, __nv_bfloat16 hi) {
    return ((uint32_t)__bfloat16_as_ushort(hi) << 16) | __bfloat16_as_ushort(lo);
}
// packed = { lo16 = bf16(losrc), hi16 = bf16(hisrc) }
__device__ __forceinline__ uint32_t cvt_pair(float hisrc, float losrc) {
    uint32_t r;
    asm("cvt.rn.bf16x2.f32 %0, %1, %2;" : "=r"(r) : "f"(hisrc), "f"(losrc));
    return r;
}
__device__ __forceinline__ int ld_acq(const int* p) {
    int v;
    asm volatile("ld.acquire.gpu.global.b32 %0, [%1];" : "=r"(v) : "l"(p) : "memory");
    return v;
}
__device__ __forceinline__ void wait_pass(int p) {
    const int* a = &g_cnt[p];
    while (ld_acq(a) < BLKS_PER_PASS) __nanosleep(128);
}

// =============== Kernel 0: one-shot W -> B-fragment conversion =============
// word index w = ((split*64 + nt*8 + s)*32 + ln)*2 + reg
// B fragment (m16n8k16.row.col): b0={B[2t][g],B[2t+1][g]}, b1 = k+8; g=ln>>2,
// t=ln&3, B[k][n] = W[n][k].
__global__ void __launch_bounds__(128) prep_bfrag(
    const float* __restrict__ Wf, const float* __restrict__ Wi,
    const float* __restrict__ Wg, const float* __restrict__ Wo)
{
    int w = blockIdx.x * 128 + threadIdx.x;
    int split = w >> 12;
    int nt = (w >> 9) & 7, s = (w >> 6) & 7;
    int ln = (w >> 1) & 31, reg = w & 1;
    int n = nt * 8 + (ln >> 2);
    int k0 = s * 16 + (ln & 3) * 2 + reg * 8;
    const float* wr = ((n < 16) ? Wf : (n < 32) ? Wi : (n < 48) ? Wg : Wo)
                      + (n & 15) * 144 + k0;
    float v0 = wr[0], v1 = wr[1];
    __nv_bfloat16 h0 = __float2bfloat16_rn(v0);
    __nv_bfloat16 h1 = __float2bfloat16_rn(v1);
    uint32_t outw;
    if (split == 0) {
        outw = pack_bf2(h0, h1);
    } else {
        __nv_bfloat16 l0 = __float2bfloat16_rn(v0 - __bfloat162float(h0));
        __nv_bfloat16 l1 = __float2bfloat16_rn(v1 - __bfloat162float(h1));
        outw = pack_bf2(l0, l1);
    }
    g_bfrag[w] = outw;
}

// ---------------- fast activations ----------------
__device__ __forceinline__ float fsigmoid(float x) {
    return __fdividef(1.f, 1.f + __expf(-x));
}
__device__ __forceinline__ float ftanh(float x) {
    float e = __expf(-2.f * x);
    return __fdividef(1.f - e, 1.f + e);
}

// ================== fused kernel: role by blockIdx.x =======================
// blocks [0,128): recurrence (all resident in wave 1; consumers).
// blocks [128, 128+4096): mma.sync split-bf16 GEMM, 2 M-tiles per block.
#define SM_BIAS 0
#define SM_BF   256                       // B frags copied from g_bfrag (32KB)
#define SM_A    (256 + 32768)             // A planes: 2 x 128 rows x 256B = 64KB
#define SM_TOT  (SM_A + 65536)            // 98560 B

__global__ void __launch_bounds__(128) fused(
    const float* __restrict__ x,
    const float* __restrict__ Wf, const float* __restrict__ bf_,
    const float* __restrict__ thf,
    const float* __restrict__ Wi, const float* __restrict__ bi_,
    const float* __restrict__ thi,
    const float* __restrict__ Wg, const float* __restrict__ bg_,
    const float* __restrict__ thg,
    const float* __restrict__ Wo, const float* __restrict__ bo_,
    const float* __restrict__ tho,
    float* __restrict__ out)
{
    extern __shared__ char smem[];
    int tid = threadIdx.x, warp = tid >> 5, lane = tid & 31;

    if (blockIdx.x >= RECUR_BLOCKS) {
        // ===================== producer: MMA GEMM ==========================
        int pbid = blockIdx.x - RECUR_BLOCKS;
        uint32_t sbase = (uint32_t)__cvta_generic_to_shared(smem);

        // bias + theta -> smem (theta folded: arg of sin is proj + matvec)
        if (tid < 64) {
            const float* bp = (tid < 16) ? bf_ : (tid < 32) ? bi_
                            : (tid < 48) ? bg_ : bo_;
            const float* tp = (tid < 16) ? thf : (tid < 32) ? thi
                            : (tid < 48) ? thg : tho;
            ((float*)(smem + SM_BIAS))[tid] = bp[tid & 15] + tp[tid & 15];
        }
        // B fragments: coalesced copy from g_bfrag (L2-resident 32KB)
#pragma unroll
        for (int i = 0; i < 16; i++)
            ((uint4*)(smem + SM_BF))[tid + 128 * i] =
                ((const uint4*)g_bfrag)[tid + 128 * i];

        int a_row = warp * 32 + (lane & 15);
        int a_hi8 = lane >> 4;

#pragma unroll 1
        for (int tile = 0; tile < 2; tile++) {
            if (tile) __syncthreads();   // protect A smem from prev mainloop

            // A: convert rows to bf16 hi/lo planes, coalesced STS.64
            size_t rowbase = (size_t)pbid * ROWS_PER_PBLK + tile * 128
                             + warp * 32;
            {
#pragma unroll 4
                for (int i = 0; i < 32; i++) {
                    float4 v = ((const float4*)x)[(rowbase + i) * 32 + lane];
                    int R = warp * 32 + i;
                    uint32_t addr = (uint32_t)(SM_A + R * 256 +
                        ((((lane >> 1) ^ (R & 7)) << 4) + (lane & 1) * 8));
                    uint32_t hi01 = cvt_pair(v.y, v.x);
                    uint32_t hi23 = cvt_pair(v.w, v.z);
                    float h0 = __uint_as_float(hi01 << 16);
                    float h1 = __uint_as_float(hi01 & 0xffff0000u);
                    float h2 = __uint_as_float(hi23 << 16);
                    float h3 = __uint_as_float(hi23 & 0xffff0000u);
                    uint32_t lo01 = cvt_pair(v.y - h1, v.x - h0);
                    uint32_t lo23 = cvt_pair(v.w - h3, v.z - h2);
                    *(uint2*)(smem + addr) = make_uint2(hi01, hi23);
                    *(uint2*)(smem + addr + 32768) = make_uint2(lo01, lo23);
                }
            }
            __syncthreads();

            float acc[2][8][4];
#pragma unroll
            for (int mt = 0; mt < 2; mt++)
#pragma unroll
                for (int nt = 0; nt < 8; nt++)
#pragma unroll
                    for (int r = 0; r < 4; r++) acc[mt][nt][r] = 0.f;

#pragma unroll 1
            for (int s = 0; s < 8; s++) {
                uint32_t af[2][2][4];
#pragma unroll
                for (int split = 0; split < 2; split++) {
#pragma unroll
                    for (int mt = 0; mt < 2; mt++) {
                        int R = a_row + mt * 16;
                        uint32_t addr = sbase + SM_A + split * 32768 + R * 256 +
                                        (((s * 2 + a_hi8) ^ (R & 7)) << 4);
                        asm volatile(
                            "ldmatrix.sync.aligned.m8n8.x4.shared.b16 "
                            "{%0,%1,%2,%3}, [%4];"
                            : "=r"(af[split][mt][0]), "=r"(af[split][mt][1]),
                              "=r"(af[split][mt][2]), "=r"(af[split][mt][3])
                            : "r"(addr));
                    }
                }
#pragma unroll
                for (int nt = 0; nt < 8; nt++) {
                    uint2 b0 = *(const uint2*)(smem + SM_BF +
                        ((((0 * 64 + nt * 8 + s) * 32) + lane) << 3));
                    uint2 b1 = *(const uint2*)(smem + SM_BF +
                        ((((1 * 64 + nt * 8 + s) * 32) + lane) << 3));
#pragma unroll
                    for (int mt = 0; mt < 2; mt++) {
#define MMA(A, BX, BY)                                                       \
    asm volatile(                                                            \
        "mma.sync.aligned.m16n8k16.row.col.f32.bf16.bf16.f32 "               \
        "{%0,%1,%2,%3}, {%4,%5,%6,%7}, {%8,%9}, {%0,%1,%2,%3};"              \
        : "+f"(acc[mt][nt][0]), "+f"(acc[mt][nt][1]),                        \
          "+f"(acc[mt][nt][2]), "+f"(acc[mt][nt][3])                         \
        : "r"((A)[0]), "r"((A)[1]), "r"((A)[2]), "r"((A)[3]),                \
          "r"(BX), "r"(BY))
                        MMA(af[0][mt], b0.x, b0.y);   // xh*wh
                        MMA(af[0][mt], b1.x, b1.y);   // xh*wl
                        MMA(af[1][mt], b0.x, b0.y);   // xl*wh
#undef MMA
                    }
                }
            }

            // epilogue: + (bias+theta), store f32 pairs
            int g = lane >> 2, t = lane & 3;
#pragma unroll
            for (int mt = 0; mt < 2; mt++) {
#pragma unroll
                for (int nt = 0; nt < 8; nt++) {
                    int col = nt * 8 + t * 2;
                    float2 bb = *(const float2*)(smem + SM_BIAS + col * 4);
                    size_t r0 = rowbase + mt * 16 + g;
                    float2 o0, o1;
                    o0.x = acc[mt][nt][0] + bb.x;
                    o0.y = acc[mt][nt][1] + bb.y;
                    o1.x = acc[mt][nt][2] + bb.x;
                    o1.y = acc[mt][nt][3] + bb.y;
                    *(float2*)(g_proj + r0 * 64 + col) = o0;
                    *(float2*)(g_proj + (r0 + 8) * 64 + col) = o1;
                }
            }
        }

        // release: all stores visible, then count this block into its pass
        __threadfence();
        __syncthreads();
        if (tid == 0) atomicAdd(&g_cnt[pbid >> 6], 1);
        return;
    }

    // ==================== consumer: recurrence =============================
    // Warp w handles batches 2w (lanes 0-15) and 2w+1 (lanes 16-31).
    // Lane owns hidden unit j = lane&15 with ALL FOUR gates.
    int w = blockIdx.x * 4 + warp;       // 0..511
    int l = tid & 31;
    int j = l & 15;
    int b = 2 * w + (l >> 4);            // this lane's batch element
    int seg = l & 16;
    const unsigned FULL = 0xffffffffu;

    // Recurrent weights for all 4 gates (theta folded into GEMM bias).
    float wr0[16], wr1[16], wr2[16], wr3[16];
#pragma unroll
    for (int k = 0; k < 16; k++) {
        wr0[k] = Wf[j * 144 + 128 + k];
        wr1[k] = Wi[j * 144 + 128 + k];
        wr2[k] = Wg[j * 144 + 128 + k];
        wr3[k] = Wo[j * 144 + 128 + k];
    }

    float h = 0.f, c = 0.f;
    const float* pp = g_proj + (size_t)b * 64 + j;
    float* op = out + (b << 4) + j;      // warp-contiguous: 2w*16 + l

    // Wait for pass 0 before preloading steps 0..3.
    wait_pass(0);
    float cur[4][4];                     // [step-in-group][gate]
#pragma unroll
    for (int u = 0; u < 4; u++) {
        cur[u][0] = pp[(size_t)u * STRIDE];
        cur[u][1] = pp[(size_t)u * STRIDE + 16];
        cur[u][2] = pp[(size_t)u * STRIDE + 32];
        cur[u][3] = pp[(size_t)u * STRIDE + 48];
    }

    for (int g = 0; g < T_STEPS / 4; g++) {
        // Next prefetch group belongs to pass (g+1)>>2; wait at pass entry.
        if (((g + 1) & 3) == 0 && ((g + 1) >> 2) < NPASS)
            wait_pass((g + 1) >> 2);

        float nxt[4][4];
#pragma unroll
        for (int u = 0; u < 4; u++) {
            nxt[u][0] = pp[(size_t)(4 + u) * STRIDE];
            nxt[u][1] = pp[(size_t)(4 + u) * STRIDE + 16];
            nxt[u][2] = pp[(size_t)(4 + u) * STRIDE + 32];
            nxt[u][3] = pp[(size_t)(4 + u) * STRIDE + 48];
        }

#pragma unroll
        for (int u = 0; u < 4; u++) {
            // ---- matvec: one shfl serves both batches; 2 partials/gate ----
            float p0a = 0.f, p0b = 0.f, p1a = 0.f, p1b = 0.f;
            float p2a = 0.f, p2b = 0.f, p3a = 0.f, p3b = 0.f;
#pragma unroll
            for (int k = 0; k < 16; k += 2) {
                float hk0 = __shfl_sync(FULL, h, seg + k + 0);
                float hk1 = __shfl_sync(FULL, h, seg + k + 1);
                p0a = fmaf(hk0, wr0[k], p0a); p0b = fmaf(hk1, wr0[k + 1], p0b);
                p1a = fmaf(hk0, wr1[k], p1a); p1b = fmaf(hk1, wr1[k + 1], p1b);
                p2a = fmaf(hk0, wr2[k], p2a); p2b = fmaf(hk1, wr2[k + 1], p2b);
                p3a = fmaf(hk0, wr3[k], p3a); p3b = fmaf(hk1, wr3[k + 1], p3b);
            }
            float a0 = cur[u][0] + (p0a + p0b);
            float a1 = cur[u][1] + (p1a + p1b);
            float a2 = cur[u][2] + (p2a + p2b);
            float a3 = cur[u][3] + (p3a + p3b);

            // ---- qgate: sin + 16-lane inclusive scan (4 gates) ----
            float s0 = __sinf(a0), s1 = __sinf(a1);
            float s2 = __sinf(a2), s3 = __sinf(a3);
            float c0 = s0, c1 = s1, c2 = s2, c3 = s3;
#pragma unroll
            for (int off = 1; off < 16; off <<= 1) {
                float u0 = __shfl_up_sync(FULL, c0, off, 16);
                float u1 = __shfl_up_sync(FULL, c1, off, 16);
                float u2 = __shfl_up_sync(FULL, c2, off, 16);
                float u3 = __shfl_up_sync(FULL, c3, off, 16);
                c0 += (j >= off) ? u0 : 0.f;
                c1 += (j >= off) ? u1 : 0.f;
                c2 += (j >= off) ? u2 : 0.f;
                c3 += (j >= off) ? u3 : 0.f;
            }
            float t0 = __shfl_sync(FULL, c0, seg + 15);
            float t1 = __shfl_sync(FULL, c1, seg + 15);
            float t2 = __shfl_sync(FULL, c2, seg + 15);
            float t3 = __shfl_sync(FULL, c3, seg + 15);
            float q0 = (j == 0) ? (s0 + t0) : c0;
            float q1 = (j == 0) ? (s1 + t1) : c1;
            float q2 = (j == 0) ? (s2 + t2) : c2;
            float q3 = (j == 0) ? (s3 + t3) : c3;

            // ---- activations + state update (all gates local) ----
            float f_ = fsigmoid(q0);
            float i_ = fsigmoid(q1);
            float g_ = ftanh(q2);
            float o_ = fsigmoid(q3);
            c = f_ * c + i_ * g_;
            h = o_ * ftanh(c);

            *op = h;                     // fully coalesced, all lanes
            op += BATCH * HID;
        }

#pragma unroll
        for (int u = 0; u < 4; u++) {
            cur[u][0] = nxt[u][0]; cur[u][1] = nxt[u][1];
            cur[u][2] = nxt[u][2]; cur[u][3] = nxt[u][3];
        }
        pp += (size_t)4 * STRIDE;
    }

    size_t base = (size_t)T_STEPS * BATCH * HID;
    out[base + (b << 4) + j] = h;
    out[base + BATCH * HID + (b << 4) + j] = c;
}

// ---------------- launch ----------------
extern "C" void kernel_launch(void* const* d_in, const int* in_sizes, int n_in,
                              void* d_out, int out_size) {
    const float* x   = (const float*)d_in[0];
    const float* Wf  = (const float*)d_in[1];
    const float* bf_ = (const float*)d_in[2];
    const float* thf = (const float*)d_in[3];
    const float* Wi  = (const float*)d_in[4];
    const float* bi_ = (const float*)d_in[5];
    const float* thi = (const float*)d_in[6];
    const float* Wg  = (const float*)d_in[7];
    const float* bg_ = (const float*)d_in[8];
    const float* thg = (const float*)d_in[9];
    const float* Wo  = (const float*)d_in[10];
    const float* bo_ = (const float*)d_in[11];
    const float* tho = (const float*)d_in[12];
    float* out = (float*)d_out;

    cudaFuncSetAttribute(fused,
                         cudaFuncAttributeMaxDynamicSharedMemorySize, SM_TOT);

    // Reset pass counters (graph-capturable async memset; no allocation).
    void* cnt_addr = nullptr;
    cudaGetSymbolAddress(&cnt_addr, g_cnt);
    cudaMemsetAsync(cnt_addr, 0, sizeof(int) * NPASS);

    prep_bfrag<<<64, 128>>>(Wf, Wi, Wg, Wo);
    fused<<<RECUR_BLOCKS + PROJ_BLOCKS, 128, SM_TOT>>>(
        x, Wf, bf_, thf, Wi, bi_, thi, Wg, bg_, thg, Wo, bo_, tho, out);
}